// round 4
// baseline (speedup 1.0000x reference)
#include <cuda_runtime.h>
#include <cuda_bf16.h>
#include <math.h>

// ---------------------------------------------------------------------------
// Problem shape (fixed by dataset): N=40000 nodes, E=640000 edges,
// C_in=128, C_hid=128, C_out=64, G=64 graphs, flat=2904.
// NOTE: edge_index and batch are int32 (JAX without x64 downgrades int64).
// ---------------------------------------------------------------------------
#define MAXN 40000
#define MAXE 640000
#define NGRAPH 64

// Scratch (static __device__ arrays; no allocation allowed)
__device__ float  g_deg[MAXN];           // degree, then overwritten with deg^{-1/2}
__device__ int    g_counts[MAXN];        // in-edge counts per node
__device__ int    g_offsets[MAXN + 1];   // CSR offsets (by destination col)
__device__ int    g_cursor[MAXN];        // scatter cursors
__device__ float2 g_csr[MAXE];           // .x = __int_as_float(src row), .y = norm weight
__device__ float  g_xw1[MAXN * 128];
__device__ float  g_h1 [MAXN * 128];
__device__ float  g_xw2[MAXN * 64];
__device__ float  g_h2 [MAXN * 64];
__device__ float  g_pool[NGRAPH * 64];
__device__ int    g_gstart[NGRAPH + 1];

// buffer selectors (compile-time, resolved in device code)
#define BUF_XW1 0
#define BUF_H1  1
#define BUF_XW2 2
#define BUF_H2  3

__device__ __forceinline__ float* buf_ptr(int which) {
    switch (which) {
        case BUF_XW1: return g_xw1;
        case BUF_H1:  return g_h1;
        case BUF_XW2: return g_xw2;
        default:      return g_h2;
    }
}

// ---------------------------------------------------------------------------
// 1. zero deg + counts
// ---------------------------------------------------------------------------
__global__ void zero_kernel(int n) {
    int i = blockIdx.x * blockDim.x + threadIdx.x;
    if (i < n) { g_deg[i] = 0.0f; g_counts[i] = 0; }
}

// ---------------------------------------------------------------------------
// 2. degree (weighted) + in-edge histogram  (edge_index: int32, [2, E])
// ---------------------------------------------------------------------------
__global__ void degree_kernel(const int* __restrict__ ei,
                              const float* __restrict__ ew, int E) {
    int e = blockIdx.x * blockDim.x + threadIdx.x;
    if (e >= E) return;
    int col = ei[E + e];
    atomicAdd(&g_deg[col], ew[e]);
    atomicAdd(&g_counts[col], 1);
}

// ---------------------------------------------------------------------------
// 3. dis = rsqrt(deg + 1)  (self-loop weight 1), in place
// ---------------------------------------------------------------------------
__global__ void dis_kernel(int n) {
    int i = blockIdx.x * blockDim.x + threadIdx.x;
    if (i < n) g_deg[i] = rsqrtf(g_deg[i] + 1.0f);
}

// ---------------------------------------------------------------------------
// 4. single-block exclusive scan of counts -> offsets (and cursor copy)
// ---------------------------------------------------------------------------
__global__ void scan_kernel(int n) {
    __shared__ int wsum[32];
    __shared__ int carry_s;
    int t = threadIdx.x, lane = t & 31, wid = t >> 5;
    if (t == 0) carry_s = 0;
    __syncthreads();
    for (int base = 0; base < n; base += 1024) {
        int idx = base + t;
        int v = (idx < n) ? g_counts[idx] : 0;
        int x = v;
        #pragma unroll
        for (int o = 1; o < 32; o <<= 1) {
            int y = __shfl_up_sync(0xFFFFFFFFu, x, o);
            if (lane >= o) x += y;
        }
        if (lane == 31) wsum[wid] = x;
        __syncthreads();
        if (wid == 0) {
            int s = wsum[lane];
            #pragma unroll
            for (int o = 1; o < 32; o <<= 1) {
                int y = __shfl_up_sync(0xFFFFFFFFu, s, o);
                if (lane >= o) s += y;
            }
            wsum[lane] = s;
        }
        __syncthreads();
        int warp_off = (wid > 0) ? wsum[wid - 1] : 0;
        int incl = x + warp_off;
        int carry = carry_s;
        if (idx < n) {
            int excl = carry + incl - v;
            g_offsets[idx] = excl;
            g_cursor[idx]  = excl;
        }
        __syncthreads();
        if (t == 1023) carry_s = carry + incl;
        __syncthreads();
    }
    if (t == 0) g_offsets[n] = carry_s;
}

// ---------------------------------------------------------------------------
// 5. build CSR entries: (src row, norm = dis[row]*ew*dis[col]) grouped by col
// ---------------------------------------------------------------------------
__global__ void build_kernel(const int* __restrict__ ei,
                             const float* __restrict__ ew, int E) {
    int e = blockIdx.x * blockDim.x + threadIdx.x;
    if (e >= E) return;
    int row = ei[e];
    int col = ei[E + e];
    int slot = atomicAdd(&g_cursor[col], 1);
    float w = g_deg[row] * ew[e] * g_deg[col];   // g_deg holds dis now
    g_csr[slot] = make_float2(__int_as_float(row), w);
}

// ---------------------------------------------------------------------------
// 6. SGEMM: C[M,BN] = A[M,128] @ B[128,BN].  BM=128, BK=8, 256 threads.
// ---------------------------------------------------------------------------
template <int BN, int TN, int SRCBUF, int DSTBUF>
__global__ void sgemm128_kernel(const float* __restrict__ Ain,
                                const float* __restrict__ B, int M) {
    constexpr int BM = 128, BK = 8;
    constexpr int NCG = BN / TN;   // 16 col groups
    const float* __restrict__ A = (SRCBUF >= 0) ? buf_ptr(SRCBUF) : Ain;
    float* __restrict__ C = buf_ptr(DSTBUF);

    __shared__ float As[BK][BM];
    __shared__ float Bs[BK][BN];
    int t  = threadIdx.x;          // 256
    int tx = t % NCG;
    int ty = t / NCG;              // 0..15, 8 rows each
    int row0 = blockIdx.x * BM;

    float acc[8][TN];
    #pragma unroll
    for (int i = 0; i < 8; i++)
        #pragma unroll
        for (int j = 0; j < TN; j++) acc[i][j] = 0.0f;

    int lr = t >> 1, lq = t & 1;   // A-tile load: row lr, 4-float chunk lq

    for (int k0 = 0; k0 < 128; k0 += BK) {
        float4 av = make_float4(0.f, 0.f, 0.f, 0.f);
        int grow = row0 + lr;
        if (grow < M)
            av = *(const float4*)(A + (size_t)grow * 128 + k0 + lq * 4);
        As[lq * 4 + 0][lr] = av.x;
        As[lq * 4 + 1][lr] = av.y;
        As[lq * 4 + 2][lr] = av.z;
        As[lq * 4 + 3][lr] = av.w;

        if (BN == 128) {
            int kk = t >> 5, c = (t & 31) * 4;
            *(float4*)&Bs[kk][c] = *(const float4*)(B + (size_t)(k0 + kk) * BN + c);
        } else {
            if (t < 128) {
                int kk = t >> 4, c = (t & 15) * 4;
                *(float4*)&Bs[kk][c] = *(const float4*)(B + (size_t)(k0 + kk) * BN + c);
            }
        }
        __syncthreads();

        #pragma unroll
        for (int kk = 0; kk < BK; kk++) {
            float a[8];
            *(float4*)&a[0] = *(float4*)&As[kk][ty * 8];
            *(float4*)&a[4] = *(float4*)&As[kk][ty * 8 + 4];
            float b[TN];
            if (TN == 8) {
                *(float4*)&b[0] = *(float4*)&Bs[kk][tx * 8];
                *(float4*)&b[4] = *(float4*)&Bs[kk][tx * 8 + 4];
            } else {
                *(float4*)&b[0] = *(float4*)&Bs[kk][tx * 4];
            }
            #pragma unroll
            for (int i = 0; i < 8; i++)
                #pragma unroll
                for (int j = 0; j < TN; j++)
                    acc[i][j] = fmaf(a[i], b[j], acc[i][j]);
        }
        __syncthreads();
    }

    #pragma unroll
    for (int i = 0; i < 8; i++) {
        int grow = row0 + ty * 8 + i;
        if (grow < M) {
            if (TN == 8) {
                *(float4*)(C + (size_t)grow * BN + tx * 8)     = *(float4*)&acc[i][0];
                *(float4*)(C + (size_t)grow * BN + tx * 8 + 4) = *(float4*)&acc[i][4];
            } else {
                *(float4*)(C + (size_t)grow * BN + tx * 4)     = *(float4*)&acc[i][0];
            }
        }
    }
}

// ---------------------------------------------------------------------------
// 7. Gather + self-loop + bias + ReLU. One warp per node.
// ---------------------------------------------------------------------------
template <int F, int SRCBUF, int DSTBUF>
__global__ void gather_kernel(const float* __restrict__ bias, int Nn) {
    const float* __restrict__ xw = buf_ptr(SRCBUF);
    float* __restrict__ outp = buf_ptr(DSTBUF);
    int warp = (blockIdx.x * blockDim.x + threadIdx.x) >> 5;
    int lane = threadIdx.x & 31;
    if (warp >= Nn) return;
    int s = g_offsets[warp];
    int e = g_offsets[warp + 1];

    if (F == 128) {
        float4 acc = make_float4(0.f, 0.f, 0.f, 0.f);
        int i = s;
        for (; i + 1 < e; i += 2) {   // unroll 2 for MLP
            float2 p0 = g_csr[i];
            float2 p1 = g_csr[i + 1];
            int s0 = __float_as_int(p0.x);
            int s1 = __float_as_int(p1.x);
            float4 x0 = *(const float4*)(xw + (size_t)s0 * 128 + lane * 4);
            float4 x1 = *(const float4*)(xw + (size_t)s1 * 128 + lane * 4);
            acc.x = fmaf(p0.y, x0.x, acc.x); acc.y = fmaf(p0.y, x0.y, acc.y);
            acc.z = fmaf(p0.y, x0.z, acc.z); acc.w = fmaf(p0.y, x0.w, acc.w);
            acc.x = fmaf(p1.y, x1.x, acc.x); acc.y = fmaf(p1.y, x1.y, acc.y);
            acc.z = fmaf(p1.y, x1.z, acc.z); acc.w = fmaf(p1.y, x1.w, acc.w);
        }
        if (i < e) {
            float2 p0 = g_csr[i];
            int s0 = __float_as_int(p0.x);
            float4 x0 = *(const float4*)(xw + (size_t)s0 * 128 + lane * 4);
            acc.x = fmaf(p0.y, x0.x, acc.x); acc.y = fmaf(p0.y, x0.y, acc.y);
            acc.z = fmaf(p0.y, x0.z, acc.z); acc.w = fmaf(p0.y, x0.w, acc.w);
        }
        float d  = g_deg[warp];
        float d2 = d * d;
        float4 sf = *(const float4*)(xw + (size_t)warp * 128 + lane * 4);
        float4 bb = *(const float4*)(bias + lane * 4);
        float4 r;
        r.x = fmaxf(fmaf(sf.x, d2, acc.x) + bb.x, 0.f);
        r.y = fmaxf(fmaf(sf.y, d2, acc.y) + bb.y, 0.f);
        r.z = fmaxf(fmaf(sf.z, d2, acc.z) + bb.z, 0.f);
        r.w = fmaxf(fmaf(sf.w, d2, acc.w) + bb.w, 0.f);
        *(float4*)(outp + (size_t)warp * 128 + lane * 4) = r;
    } else {
        float2 acc = make_float2(0.f, 0.f);
        int i = s;
        for (; i + 1 < e; i += 2) {
            float2 p0 = g_csr[i];
            float2 p1 = g_csr[i + 1];
            int s0 = __float_as_int(p0.x);
            int s1 = __float_as_int(p1.x);
            float2 x0 = *(const float2*)(xw + (size_t)s0 * 64 + lane * 2);
            float2 x1 = *(const float2*)(xw + (size_t)s1 * 64 + lane * 2);
            acc.x = fmaf(p0.y, x0.x, acc.x); acc.y = fmaf(p0.y, x0.y, acc.y);
            acc.x = fmaf(p1.y, x1.x, acc.x); acc.y = fmaf(p1.y, x1.y, acc.y);
        }
        if (i < e) {
            float2 p0 = g_csr[i];
            int s0 = __float_as_int(p0.x);
            float2 x0 = *(const float2*)(xw + (size_t)s0 * 64 + lane * 2);
            acc.x = fmaf(p0.y, x0.x, acc.x); acc.y = fmaf(p0.y, x0.y, acc.y);
        }
        float d  = g_deg[warp];
        float d2 = d * d;
        float2 sf = *(const float2*)(xw + (size_t)warp * 64 + lane * 2);
        float2 bb = *(const float2*)(bias + lane * 2);
        float2 r;
        r.x = fmaxf(fmaf(sf.x, d2, acc.x) + bb.x, 0.f);
        r.y = fmaxf(fmaf(sf.y, d2, acc.y) + bb.y, 0.f);
        *(float2*)(outp + (size_t)warp * 64 + lane * 2) = r;
    }
}

// ---------------------------------------------------------------------------
// 8. graph boundaries via binary search (batch is sorted, int32)
// ---------------------------------------------------------------------------
__global__ void bounds_kernel(const int* __restrict__ batch, int N) {
    int g = threadIdx.x;
    if (g > NGRAPH) return;
    int lo = 0, hi = N;
    while (lo < hi) {
        int mid = (lo + hi) >> 1;
        if (batch[mid] < g) lo = mid + 1; else hi = mid;
    }
    g_gstart[g] = lo;
}

// ---------------------------------------------------------------------------
// 9. global mean pool: one block per graph
// ---------------------------------------------------------------------------
__global__ void pool_kernel() {
    int g = blockIdx.x;
    int t = threadIdx.x;           // 256
    int f   = t & 63;
    int sub = t >> 6;              // 0..3
    int s = g_gstart[g], e = g_gstart[g + 1];
    float acc = 0.0f;
    for (int i = s + sub; i < e; i += 4)
        acc += g_h2[(size_t)i * 64 + f];
    __shared__ float red[256];
    red[t] = acc;
    __syncthreads();
    if (t < 64) {
        float v = red[t] + red[t + 64] + red[t + 128] + red[t + 192];
        float cnt = (float)(e - s);
        g_pool[g * 64 + t] = v / fmaxf(cnt, 1.0f);
    }
}

// ---------------------------------------------------------------------------
// 10. FC: out[g, j] = pool[g,:] @ Wfc[:, j] + bfc[j]
// ---------------------------------------------------------------------------
__global__ void fc_kernel(const float* __restrict__ Wfc,
                          const float* __restrict__ bfc,
                          float* __restrict__ out, int flat) {
    int idx = blockIdx.x * blockDim.x + threadIdx.x;
    int tot = NGRAPH * flat;
    if (idx >= tot) return;
    int g = idx / flat;
    int j = idx - g * flat;
    const float* pg = g_pool + g * 64;
    float s = bfc[j];
    #pragma unroll 8
    for (int k = 0; k < 64; k++)
        s = fmaf(pg[k], Wfc[(size_t)k * flat + j], s);
    out[idx] = s;
}

// ---------------------------------------------------------------------------
// launch (kernel launches ONLY — must be graph-capturable)
// ---------------------------------------------------------------------------
extern "C" void kernel_launch(void* const* d_in, const int* in_sizes, int n_in,
                              void* d_out, int out_size) {
    const float* x     = (const float*)d_in[0];
    const int*   ei    = (const int*)d_in[1];     // int32 (JAX default)
    const float* ew    = (const float*)d_in[2];
    const int*   batch = (const int*)d_in[3];     // int32
    const float* W1    = (const float*)d_in[4];
    const float* b1    = (const float*)d_in[5];
    const float* W2    = (const float*)d_in[6];
    const float* b2    = (const float*)d_in[7];
    const float* Wfc   = (const float*)d_in[8];
    const float* bfc   = (const float*)d_in[9];
    float* out = (float*)d_out;

    int N    = in_sizes[0] / 128;   // 40000
    int E    = in_sizes[2];         // 640000
    int flat = in_sizes[8] / 64;    // 2904

    int tb = 256;
    zero_kernel<<<(N + tb - 1) / tb, tb>>>(N);
    degree_kernel<<<(E + tb - 1) / tb, tb>>>(ei, ew, E);
    dis_kernel<<<(N + tb - 1) / tb, tb>>>(N);
    scan_kernel<<<1, 1024>>>(N);
    build_kernel<<<(E + tb - 1) / tb, tb>>>(ei, ew, E);

    // layer 1: xw1 = x @ W1 ; h1 = relu(agg(xw1) + b1)
    sgemm128_kernel<128, 8, -1, BUF_XW1><<<(N + 127) / 128, 256>>>(x, W1, N);
    gather_kernel<128, BUF_XW1, BUF_H1><<<(N + 7) / 8, 256>>>(b1, N);

    // layer 2: xw2 = h1 @ W2 ; h2 = relu(agg(xw2) + b2)
    sgemm128_kernel<64, 4, BUF_H1, BUF_XW2><<<(N + 127) / 128, 256>>>(nullptr, W2, N);
    gather_kernel<64, BUF_XW2, BUF_H2><<<(N + 7) / 8, 256>>>(b2, N);

    // pool + fc
    bounds_kernel<<<1, 128>>>(batch, N);
    pool_kernel<<<NGRAPH, 256>>>();
    fc_kernel<<<(NGRAPH * flat + tb - 1) / tb, tb>>>(Wfc, bfc, out, flat);
}

// round 5
// speedup vs baseline: 1.1277x; 1.1277x over previous
#include <cuda_runtime.h>
#include <cuda_bf16.h>
#include <math.h>

// ---------------------------------------------------------------------------
// Problem shape (fixed by dataset): N=40000 nodes, E=640000 edges,
// C_in=128, C_hid=128, C_out=64, G=64 graphs, flat=2904.
// edge_index and batch are int32.
// ---------------------------------------------------------------------------
#define MAXN 40000
#define MAXE 640000
#define NGRAPH 64
#define SCAN_CHUNK 1024
#define MAXPART 64          // ceil(MAXN/1024) = 40 <= 64

// Scratch (static __device__ arrays; no allocation allowed)
__device__ float  g_deg[MAXN];
__device__ int    g_counts[MAXN];
__device__ int    g_offsets[MAXN + 1];
__device__ int    g_cursor[MAXN];
__device__ int    g_part[MAXPART];
__device__ float2 g_csr[MAXE];
__device__ float  g_xw1[MAXN * 128];
__device__ float  g_h1 [MAXN * 128];
__device__ float  g_xw2[MAXN * 64];
__device__ float  g_h2 [MAXN * 64];
__device__ float  g_pool[NGRAPH * 64];
__device__ int    g_gstart[NGRAPH + 1];

#define BUF_XW1 0
#define BUF_H1  1
#define BUF_XW2 2
#define BUF_H2  3

__device__ __forceinline__ float* buf_ptr(int which) {
    switch (which) {
        case BUF_XW1: return g_xw1;
        case BUF_H1:  return g_h1;
        case BUF_XW2: return g_xw2;
        default:      return g_h2;
    }
}

// ---------------------------------------------------------------------------
// 1. zero deg + counts
// ---------------------------------------------------------------------------
__global__ void zero_kernel(int n) {
    int i = blockIdx.x * blockDim.x + threadIdx.x;
    if (i < n) { g_deg[i] = 0.0f; g_counts[i] = 0; }
}

// ---------------------------------------------------------------------------
// 2. degree (weighted) + in-edge histogram
// ---------------------------------------------------------------------------
__global__ void degree_kernel(const int* __restrict__ ei,
                              const float* __restrict__ ew, int E) {
    int e = blockIdx.x * blockDim.x + threadIdx.x;
    if (e >= E) return;
    int col = ei[E + e];
    atomicAdd(&g_deg[col], ew[e]);
    atomicAdd(&g_counts[col], 1);
}

// ---------------------------------------------------------------------------
// 3. dis = rsqrt(deg + 1), in place
// ---------------------------------------------------------------------------
__global__ void dis_kernel(int n) {
    int i = blockIdx.x * blockDim.x + threadIdx.x;
    if (i < n) g_deg[i] = rsqrtf(g_deg[i] + 1.0f);
}

// ---------------------------------------------------------------------------
// 4a. per-chunk sums: block b reduces counts[b*1024 .. b*1024+1023]
// ---------------------------------------------------------------------------
__global__ void scan_part_kernel(int n) {
    __shared__ int warp_sums[8];
    int t = threadIdx.x;                 // 256
    int base = blockIdx.x * SCAN_CHUNK;
    int s = 0;
    #pragma unroll
    for (int j = 0; j < 4; j++) {
        int idx = base + t * 4 + j;
        if (idx < n) s += g_counts[idx];
    }
    #pragma unroll
    for (int o = 16; o > 0; o >>= 1) s += __shfl_down_sync(0xFFFFFFFFu, s, o);
    if ((t & 31) == 0) warp_sums[t >> 5] = s;
    __syncthreads();
    if (t < 8) {
        int v = warp_sums[t];
        #pragma unroll
        for (int o = 4; o > 0; o >>= 1) v += __shfl_down_sync(0xFFu, v, o);
        if (t == 0) g_part[blockIdx.x] = v;
    }
}

// ---------------------------------------------------------------------------
// 4b. spine: 1 warp exclusive-scans npart (<=64) partials, writes offsets[n]=E
// ---------------------------------------------------------------------------
__global__ void scan_spine_kernel(int npart, int n, int E) {
    int lane = threadIdx.x;              // 32
    int a = (lane * 2     < npart) ? g_part[lane * 2]     : 0;
    int b = (lane * 2 + 1 < npart) ? g_part[lane * 2 + 1] : 0;
    int s = a + b;
    int x = s;
    #pragma unroll
    for (int o = 1; o < 32; o <<= 1) {
        int y = __shfl_up_sync(0xFFFFFFFFu, x, o);
        if (lane >= o) x += y;
    }
    int excl = x - s;                    // exclusive prefix of pair-sum
    if (lane * 2     < npart) g_part[lane * 2]     = excl;
    if (lane * 2 + 1 < npart) g_part[lane * 2 + 1] = excl + a;
    if (lane == 0) g_offsets[n] = E;
}

// ---------------------------------------------------------------------------
// 4c. final: block rescans its chunk, adds spine offset, writes offsets+cursor
// ---------------------------------------------------------------------------
__global__ void scan_final_kernel(int n) {
    __shared__ int warp_sums[8];
    int t = threadIdx.x, lane = t & 31, wid = t >> 5;
    int base = blockIdx.x * SCAN_CHUNK;
    int v[4], p = 0;
    #pragma unroll
    for (int j = 0; j < 4; j++) {
        int idx = base + t * 4 + j;
        v[j] = (idx < n) ? g_counts[idx] : 0;
        p += v[j];
    }
    int x = p;
    #pragma unroll
    for (int o = 1; o < 32; o <<= 1) {
        int y = __shfl_up_sync(0xFFFFFFFFu, x, o);
        if (lane >= o) x += y;
    }
    if (lane == 31) warp_sums[wid] = x;
    __syncthreads();
    if (t < 8) {
        int s = warp_sums[t];
        #pragma unroll
        for (int o = 1; o < 8; o <<= 1) {
            int y = __shfl_up_sync(0xFFu, s, o);
            if (t >= o) s += y;
        }
        warp_sums[t] = s;
    }
    __syncthreads();
    int bexcl = g_part[blockIdx.x] + ((wid > 0) ? warp_sums[wid - 1] : 0) + (x - p);
    #pragma unroll
    for (int j = 0; j < 4; j++) {
        int idx = base + t * 4 + j;
        if (idx < n) { g_offsets[idx] = bexcl; g_cursor[idx] = bexcl; }
        bexcl += v[j];
    }
}

// ---------------------------------------------------------------------------
// 5. build CSR entries: (src row, norm) grouped by col
// ---------------------------------------------------------------------------
__global__ void build_kernel(const int* __restrict__ ei,
                             const float* __restrict__ ew, int E) {
    int e = blockIdx.x * blockDim.x + threadIdx.x;
    if (e >= E) return;
    int row = ei[e];
    int col = ei[E + e];
    int slot = atomicAdd(&g_cursor[col], 1);
    float w = g_deg[row] * ew[e] * g_deg[col];
    g_csr[slot] = make_float2(__int_as_float(row), w);
}

// ---------------------------------------------------------------------------
// 6. SGEMM: C[M,BN] = A[M,128] @ B[128,BN].  BM=128, BK=8, 256 threads.
// ---------------------------------------------------------------------------
template <int BN, int TN, int SRCBUF, int DSTBUF>
__global__ void sgemm128_kernel(const float* __restrict__ Ain,
                                const float* __restrict__ B, int M) {
    constexpr int BM = 128, BK = 8;
    constexpr int NCG = BN / TN;
    const float* __restrict__ A = (SRCBUF >= 0) ? buf_ptr(SRCBUF) : Ain;
    float* __restrict__ C = buf_ptr(DSTBUF);

    __shared__ float As[BK][BM];
    __shared__ float Bs[BK][BN];
    int t  = threadIdx.x;
    int tx = t % NCG;
    int ty = t / NCG;
    int row0 = blockIdx.x * BM;

    float acc[8][TN];
    #pragma unroll
    for (int i = 0; i < 8; i++)
        #pragma unroll
        for (int j = 0; j < TN; j++) acc[i][j] = 0.0f;

    int lr = t >> 1, lq = t & 1;

    for (int k0 = 0; k0 < 128; k0 += BK) {
        float4 av = make_float4(0.f, 0.f, 0.f, 0.f);
        int grow = row0 + lr;
        if (grow < M)
            av = *(const float4*)(A + (size_t)grow * 128 + k0 + lq * 4);
        As[lq * 4 + 0][lr] = av.x;
        As[lq * 4 + 1][lr] = av.y;
        As[lq * 4 + 2][lr] = av.z;
        As[lq * 4 + 3][lr] = av.w;

        if (BN == 128) {
            int kk = t >> 5, c = (t & 31) * 4;
            *(float4*)&Bs[kk][c] = *(const float4*)(B + (size_t)(k0 + kk) * BN + c);
        } else {
            if (t < 128) {
                int kk = t >> 4, c = (t & 15) * 4;
                *(float4*)&Bs[kk][c] = *(const float4*)(B + (size_t)(k0 + kk) * BN + c);
            }
        }
        __syncthreads();

        #pragma unroll
        for (int kk = 0; kk < BK; kk++) {
            float a[8];
            *(float4*)&a[0] = *(float4*)&As[kk][ty * 8];
            *(float4*)&a[4] = *(float4*)&As[kk][ty * 8 + 4];
            float b[TN];
            if (TN == 8) {
                *(float4*)&b[0] = *(float4*)&Bs[kk][tx * 8];
                *(float4*)&b[4] = *(float4*)&Bs[kk][tx * 8 + 4];
            } else {
                *(float4*)&b[0] = *(float4*)&Bs[kk][tx * 4];
            }
            #pragma unroll
            for (int i = 0; i < 8; i++)
                #pragma unroll
                for (int j = 0; j < TN; j++)
                    acc[i][j] = fmaf(a[i], b[j], acc[i][j]);
        }
        __syncthreads();
    }

    #pragma unroll
    for (int i = 0; i < 8; i++) {
        int grow = row0 + ty * 8 + i;
        if (grow < M) {
            if (TN == 8) {
                *(float4*)(C + (size_t)grow * BN + tx * 8)     = *(float4*)&acc[i][0];
                *(float4*)(C + (size_t)grow * BN + tx * 8 + 4) = *(float4*)&acc[i][4];
            } else {
                *(float4*)(C + (size_t)grow * BN + tx * 4)     = *(float4*)&acc[i][0];
            }
        }
    }
}

// ---------------------------------------------------------------------------
// 7. Gather + self-loop + bias + ReLU. One warp per node.
// ---------------------------------------------------------------------------
template <int F, int SRCBUF, int DSTBUF>
__global__ void gather_kernel(const float* __restrict__ bias, int Nn) {
    const float* __restrict__ xw = buf_ptr(SRCBUF);
    float* __restrict__ outp = buf_ptr(DSTBUF);
    int warp = (blockIdx.x * blockDim.x + threadIdx.x) >> 5;
    int lane = threadIdx.x & 31;
    if (warp >= Nn) return;
    int s = g_offsets[warp];
    int e = g_offsets[warp + 1];

    if (F == 128) {
        float4 acc = make_float4(0.f, 0.f, 0.f, 0.f);
        int i = s;
        for (; i + 1 < e; i += 2) {
            float2 p0 = g_csr[i];
            float2 p1 = g_csr[i + 1];
            int s0 = __float_as_int(p0.x);
            int s1 = __float_as_int(p1.x);
            float4 x0 = *(const float4*)(xw + (size_t)s0 * 128 + lane * 4);
            float4 x1 = *(const float4*)(xw + (size_t)s1 * 128 + lane * 4);
            acc.x = fmaf(p0.y, x0.x, acc.x); acc.y = fmaf(p0.y, x0.y, acc.y);
            acc.z = fmaf(p0.y, x0.z, acc.z); acc.w = fmaf(p0.y, x0.w, acc.w);
            acc.x = fmaf(p1.y, x1.x, acc.x); acc.y = fmaf(p1.y, x1.y, acc.y);
            acc.z = fmaf(p1.y, x1.z, acc.z); acc.w = fmaf(p1.y, x1.w, acc.w);
        }
        if (i < e) {
            float2 p0 = g_csr[i];
            int s0 = __float_as_int(p0.x);
            float4 x0 = *(const float4*)(xw + (size_t)s0 * 128 + lane * 4);
            acc.x = fmaf(p0.y, x0.x, acc.x); acc.y = fmaf(p0.y, x0.y, acc.y);
            acc.z = fmaf(p0.y, x0.z, acc.z); acc.w = fmaf(p0.y, x0.w, acc.w);
        }
        float d  = g_deg[warp];
        float d2 = d * d;
        float4 sf = *(const float4*)(xw + (size_t)warp * 128 + lane * 4);
        float4 bb = *(const float4*)(bias + lane * 4);
        float4 r;
        r.x = fmaxf(fmaf(sf.x, d2, acc.x) + bb.x, 0.f);
        r.y = fmaxf(fmaf(sf.y, d2, acc.y) + bb.y, 0.f);
        r.z = fmaxf(fmaf(sf.z, d2, acc.z) + bb.z, 0.f);
        r.w = fmaxf(fmaf(sf.w, d2, acc.w) + bb.w, 0.f);
        *(float4*)(outp + (size_t)warp * 128 + lane * 4) = r;
    } else {
        float2 acc = make_float2(0.f, 0.f);
        int i = s;
        for (; i + 1 < e; i += 2) {
            float2 p0 = g_csr[i];
            float2 p1 = g_csr[i + 1];
            int s0 = __float_as_int(p0.x);
            int s1 = __float_as_int(p1.x);
            float2 x0 = *(const float2*)(xw + (size_t)s0 * 64 + lane * 2);
            float2 x1 = *(const float2*)(xw + (size_t)s1 * 64 + lane * 2);
            acc.x = fmaf(p0.y, x0.x, acc.x); acc.y = fmaf(p0.y, x0.y, acc.y);
            acc.x = fmaf(p1.y, x1.x, acc.x); acc.y = fmaf(p1.y, x1.y, acc.y);
        }
        if (i < e) {
            float2 p0 = g_csr[i];
            int s0 = __float_as_int(p0.x);
            float2 x0 = *(const float2*)(xw + (size_t)s0 * 64 + lane * 2);
            acc.x = fmaf(p0.y, x0.x, acc.x); acc.y = fmaf(p0.y, x0.y, acc.y);
        }
        float d  = g_deg[warp];
        float d2 = d * d;
        float2 sf = *(const float2*)(xw + (size_t)warp * 64 + lane * 2);
        float2 bb = *(const float2*)(bias + lane * 2);
        float2 r;
        r.x = fmaxf(fmaf(sf.x, d2, acc.x) + bb.x, 0.f);
        r.y = fmaxf(fmaf(sf.y, d2, acc.y) + bb.y, 0.f);
        *(float2*)(outp + (size_t)warp * 64 + lane * 2) = r;
    }
}

// ---------------------------------------------------------------------------
// 8. graph boundaries via binary search (batch is sorted, int32)
// ---------------------------------------------------------------------------
__global__ void bounds_kernel(const int* __restrict__ batch, int N) {
    int g = threadIdx.x;
    if (g > NGRAPH) return;
    int lo = 0, hi = N;
    while (lo < hi) {
        int mid = (lo + hi) >> 1;
        if (batch[mid] < g) lo = mid + 1; else hi = mid;
    }
    g_gstart[g] = lo;
}

// ---------------------------------------------------------------------------
// 9. global mean pool: one block per graph
// ---------------------------------------------------------------------------
__global__ void pool_kernel() {
    int g = blockIdx.x;
    int t = threadIdx.x;           // 256
    int f   = t & 63;
    int sub = t >> 6;
    int s = g_gstart[g], e = g_gstart[g + 1];
    float acc = 0.0f;
    for (int i = s + sub; i < e; i += 4)
        acc += g_h2[(size_t)i * 64 + f];
    __shared__ float red[256];
    red[t] = acc;
    __syncthreads();
    if (t < 64) {
        float v = red[t] + red[t + 64] + red[t + 128] + red[t + 192];
        float cnt = (float)(e - s);
        g_pool[g * 64 + t] = v / fmaxf(cnt, 1.0f);
    }
}

// ---------------------------------------------------------------------------
// 10. FC: out[g, j] = pool[g,:] @ Wfc[:, j] + bfc[j]
// ---------------------------------------------------------------------------
__global__ void fc_kernel(const float* __restrict__ Wfc,
                          const float* __restrict__ bfc,
                          float* __restrict__ out, int flat) {
    int idx = blockIdx.x * blockDim.x + threadIdx.x;
    int tot = NGRAPH * flat;
    if (idx >= tot) return;
    int g = idx / flat;
    int j = idx - g * flat;
    const float* pg = g_pool + g * 64;
    float s = bfc[j];
    #pragma unroll 8
    for (int k = 0; k < 64; k++)
        s = fmaf(pg[k], Wfc[(size_t)k * flat + j], s);
    out[idx] = s;
}

// ---------------------------------------------------------------------------
// launch (kernel launches ONLY — must be graph-capturable)
// ---------------------------------------------------------------------------
extern "C" void kernel_launch(void* const* d_in, const int* in_sizes, int n_in,
                              void* d_out, int out_size) {
    const float* x     = (const float*)d_in[0];
    const int*   ei    = (const int*)d_in[1];
    const float* ew    = (const float*)d_in[2];
    const int*   batch = (const int*)d_in[3];
    const float* W1    = (const float*)d_in[4];
    const float* b1    = (const float*)d_in[5];
    const float* W2    = (const float*)d_in[6];
    const float* b2    = (const float*)d_in[7];
    const float* Wfc   = (const float*)d_in[8];
    const float* bfc   = (const float*)d_in[9];
    float* out = (float*)d_out;

    int N    = in_sizes[0] / 128;   // 40000
    int E    = in_sizes[2];         // 640000
    int flat = in_sizes[8] / 64;    // 2904
    int npart = (N + SCAN_CHUNK - 1) / SCAN_CHUNK;   // 40

    int tb = 256;
    zero_kernel<<<(N + tb - 1) / tb, tb>>>(N);
    degree_kernel<<<(E + tb - 1) / tb, tb>>>(ei, ew, E);
    dis_kernel<<<(N + tb - 1) / tb, tb>>>(N);
    scan_part_kernel<<<npart, 256>>>(N);
    scan_spine_kernel<<<1, 32>>>(npart, N, E);
    scan_final_kernel<<<npart, 256>>>(N);
    build_kernel<<<(E + tb - 1) / tb, tb>>>(ei, ew, E);

    // layer 1
    sgemm128_kernel<128, 8, -1, BUF_XW1><<<(N + 127) / 128, 256>>>(x, W1, N);
    gather_kernel<128, BUF_XW1, BUF_H1><<<(N + 7) / 8, 256>>>(b1, N);

    // layer 2
    sgemm128_kernel<64, 4, BUF_H1, BUF_XW2><<<(N + 127) / 128, 256>>>(nullptr, W2, N);
    gather_kernel<64, BUF_XW2, BUF_H2><<<(N + 7) / 8, 256>>>(b2, N);

    // pool + fc
    bounds_kernel<<<1, 128>>>(batch, N);
    pool_kernel<<<NGRAPH, 256>>>();
    fc_kernel<<<(NGRAPH * flat + tb - 1) / tb, tb>>>(Wfc, bfc, out, flat);
}

// round 6
// speedup vs baseline: 1.2542x; 1.1121x over previous
#include <cuda_runtime.h>
#include <cuda_bf16.h>
#include <math.h>

// ---------------------------------------------------------------------------
// N=40000, E=640000, C_in=128, C_hid=128, C_out=64, G=64, flat=2904.
// edge_index and batch are int32.
// ---------------------------------------------------------------------------
#define MAXN 40000
#define MAXE 640000
#define NGRAPH 64
#define SCAN_CHUNK 1024
#define MAXPART 64

__device__ float  g_deg[MAXN];
__device__ int    g_counts[MAXN];
__device__ int    g_offsets[MAXN + 1];
__device__ int    g_cursor[MAXN];
__device__ int    g_part[MAXPART];
__device__ float2 g_csr[MAXE];
__device__ float  g_xw1[MAXN * 128];
__device__ float  g_h1 [MAXN * 128];
__device__ float  g_xw2[MAXN * 64];
__device__ float  g_h2 [MAXN * 64];
__device__ float  g_pool[NGRAPH * 64];
__device__ int    g_gstart[NGRAPH + 1];

#define BUF_XW1 0
#define BUF_H1  1
#define BUF_XW2 2
#define BUF_H2  3

__device__ __forceinline__ float* buf_ptr(int which) {
    switch (which) {
        case BUF_XW1: return g_xw1;
        case BUF_H1:  return g_h1;
        case BUF_XW2: return g_xw2;
        default:      return g_h2;
    }
}

// ---------------------------------------------------------------------------
__global__ void zero_kernel(int n) {
    int i = blockIdx.x * blockDim.x + threadIdx.x;
    if (i < n) { g_deg[i] = 0.0f; g_counts[i] = 0; }
}

__global__ void degree_kernel(const int* __restrict__ ei,
                              const float* __restrict__ ew, int E) {
    int e = blockIdx.x * blockDim.x + threadIdx.x;
    if (e >= E) return;
    int col = ei[E + e];
    atomicAdd(&g_deg[col], ew[e]);
    atomicAdd(&g_counts[col], 1);
}

// ---------------------------------------------------------------------------
// scan_part: per-chunk sum of counts, FUSED with dis = rsqrt(deg+1)
// (grid covers all N indices; runs after degree_kernel on the same stream)
// ---------------------------------------------------------------------------
__global__ void scan_part_kernel(int n) {
    __shared__ int warp_sums[8];
    int t = threadIdx.x;                 // 256
    int base = blockIdx.x * SCAN_CHUNK;
    int s = 0;
    #pragma unroll
    for (int j = 0; j < 4; j++) {
        int idx = base + t * 4 + j;
        if (idx < n) {
            s += g_counts[idx];
            g_deg[idx] = rsqrtf(g_deg[idx] + 1.0f);   // fused dis
        }
    }
    #pragma unroll
    for (int o = 16; o > 0; o >>= 1) s += __shfl_down_sync(0xFFFFFFFFu, s, o);
    if ((t & 31) == 0) warp_sums[t >> 5] = s;
    __syncthreads();
    if (t < 8) {
        int v = warp_sums[t];
        #pragma unroll
        for (int o = 4; o > 0; o >>= 1) v += __shfl_down_sync(0xFFu, v, o);
        if (t == 0) g_part[blockIdx.x] = v;
    }
}

__global__ void scan_spine_kernel(int npart, int n, int E) {
    int lane = threadIdx.x;              // 32
    int a = (lane * 2     < npart) ? g_part[lane * 2]     : 0;
    int b = (lane * 2 + 1 < npart) ? g_part[lane * 2 + 1] : 0;
    int s = a + b;
    int x = s;
    #pragma unroll
    for (int o = 1; o < 32; o <<= 1) {
        int y = __shfl_up_sync(0xFFFFFFFFu, x, o);
        if (lane >= o) x += y;
    }
    int excl = x - s;
    if (lane * 2     < npart) g_part[lane * 2]     = excl;
    if (lane * 2 + 1 < npart) g_part[lane * 2 + 1] = excl + a;
    if (lane == 0) g_offsets[n] = E;
}

__global__ void scan_final_kernel(int n) {
    __shared__ int warp_sums[8];
    int t = threadIdx.x, lane = t & 31, wid = t >> 5;
    int base = blockIdx.x * SCAN_CHUNK;
    int v[4], p = 0;
    #pragma unroll
    for (int j = 0; j < 4; j++) {
        int idx = base + t * 4 + j;
        v[j] = (idx < n) ? g_counts[idx] : 0;
        p += v[j];
    }
    int x = p;
    #pragma unroll
    for (int o = 1; o < 32; o <<= 1) {
        int y = __shfl_up_sync(0xFFFFFFFFu, x, o);
        if (lane >= o) x += y;
    }
    if (lane == 31) warp_sums[wid] = x;
    __syncthreads();
    if (t < 8) {
        int s = warp_sums[t];
        #pragma unroll
        for (int o = 1; o < 8; o <<= 1) {
            int y = __shfl_up_sync(0xFFu, s, o);
            if (t >= o) s += y;
        }
        warp_sums[t] = s;
    }
    __syncthreads();
    int bexcl = g_part[blockIdx.x] + ((wid > 0) ? warp_sums[wid - 1] : 0) + (x - p);
    #pragma unroll
    for (int j = 0; j < 4; j++) {
        int idx = base + t * 4 + j;
        if (idx < n) { g_offsets[idx] = bexcl; g_cursor[idx] = bexcl; }
        bexcl += v[j];
    }
}

__global__ void build_kernel(const int* __restrict__ ei,
                             const float* __restrict__ ew, int E) {
    int e = blockIdx.x * blockDim.x + threadIdx.x;
    if (e >= E) return;
    int row = ei[e];
    int col = ei[E + e];
    int slot = atomicAdd(&g_cursor[col], 1);
    float w = g_deg[row] * ew[e] * g_deg[col];
    g_csr[slot] = make_float2(__int_as_float(row), w);
}

// ---------------------------------------------------------------------------
// SGEMM: C[M,BN] = A[M,128] @ B[128,BN].  BM=128, BK=8, 256 threads.
// ---------------------------------------------------------------------------
template <int BN, int TN, int SRCBUF, int DSTBUF>
__global__ void sgemm128_kernel(const float* __restrict__ Ain,
                                const float* __restrict__ B, int M) {
    constexpr int BM = 128, BK = 8;
    constexpr int NCG = BN / TN;
    const float* __restrict__ A = (SRCBUF >= 0) ? buf_ptr(SRCBUF) : Ain;
    float* __restrict__ C = buf_ptr(DSTBUF);

    __shared__ float As[BK][BM];
    __shared__ float Bs[BK][BN];
    int t  = threadIdx.x;
    int tx = t % NCG;
    int ty = t / NCG;
    int row0 = blockIdx.x * BM;

    float acc[8][TN];
    #pragma unroll
    for (int i = 0; i < 8; i++)
        #pragma unroll
        for (int j = 0; j < TN; j++) acc[i][j] = 0.0f;

    int lr = t >> 1, lq = t & 1;

    for (int k0 = 0; k0 < 128; k0 += BK) {
        float4 av = make_float4(0.f, 0.f, 0.f, 0.f);
        int grow = row0 + lr;
        if (grow < M)
            av = *(const float4*)(A + (size_t)grow * 128 + k0 + lq * 4);
        As[lq * 4 + 0][lr] = av.x;
        As[lq * 4 + 1][lr] = av.y;
        As[lq * 4 + 2][lr] = av.z;
        As[lq * 4 + 3][lr] = av.w;

        if (BN == 128) {
            int kk = t >> 5, c = (t & 31) * 4;
            *(float4*)&Bs[kk][c] = *(const float4*)(B + (size_t)(k0 + kk) * BN + c);
        } else {
            if (t < 128) {
                int kk = t >> 4, c = (t & 15) * 4;
                *(float4*)&Bs[kk][c] = *(const float4*)(B + (size_t)(k0 + kk) * BN + c);
            }
        }
        __syncthreads();

        #pragma unroll
        for (int kk = 0; kk < BK; kk++) {
            float a[8];
            *(float4*)&a[0] = *(float4*)&As[kk][ty * 8];
            *(float4*)&a[4] = *(float4*)&As[kk][ty * 8 + 4];
            float b[TN];
            if (TN == 8) {
                *(float4*)&b[0] = *(float4*)&Bs[kk][tx * 8];
                *(float4*)&b[4] = *(float4*)&Bs[kk][tx * 8 + 4];
            } else {
                *(float4*)&b[0] = *(float4*)&Bs[kk][tx * 4];
            }
            #pragma unroll
            for (int i = 0; i < 8; i++)
                #pragma unroll
                for (int j = 0; j < TN; j++)
                    acc[i][j] = fmaf(a[i], b[j], acc[i][j]);
        }
        __syncthreads();
    }

    #pragma unroll
    for (int i = 0; i < 8; i++) {
        int grow = row0 + ty * 8 + i;
        if (grow < M) {
            if (TN == 8) {
                *(float4*)(C + (size_t)grow * BN + tx * 8)     = *(float4*)&acc[i][0];
                *(float4*)(C + (size_t)grow * BN + tx * 8 + 4) = *(float4*)&acc[i][4];
            } else {
                *(float4*)(C + (size_t)grow * BN + tx * 4)     = *(float4*)&acc[i][0];
            }
        }
    }
}

// ---------------------------------------------------------------------------
// Gather + self-loop + bias + ReLU. One warp per node, unroll 4.
// ---------------------------------------------------------------------------
template <int F, int SRCBUF, int DSTBUF>
__global__ void gather_kernel(const float* __restrict__ bias, int Nn) {
    const float* __restrict__ xw = buf_ptr(SRCBUF);
    float* __restrict__ outp = buf_ptr(DSTBUF);
    int warp = (blockIdx.x * blockDim.x + threadIdx.x) >> 5;
    int lane = threadIdx.x & 31;
    if (warp >= Nn) return;
    int s = g_offsets[warp];
    int e = g_offsets[warp + 1];

    if (F == 128) {
        float4 acc = make_float4(0.f, 0.f, 0.f, 0.f);
        int i = s;
        for (; i + 3 < e; i += 4) {
            float2 p0 = g_csr[i],     p1 = g_csr[i + 1];
            float2 p2 = g_csr[i + 2], p3 = g_csr[i + 3];
            const float* r0 = xw + (size_t)__float_as_int(p0.x) * 128 + lane * 4;
            const float* r1 = xw + (size_t)__float_as_int(p1.x) * 128 + lane * 4;
            const float* r2 = xw + (size_t)__float_as_int(p2.x) * 128 + lane * 4;
            const float* r3 = xw + (size_t)__float_as_int(p3.x) * 128 + lane * 4;
            float4 x0 = *(const float4*)r0;
            float4 x1 = *(const float4*)r1;
            float4 x2 = *(const float4*)r2;
            float4 x3 = *(const float4*)r3;
            acc.x = fmaf(p0.y, x0.x, acc.x); acc.y = fmaf(p0.y, x0.y, acc.y);
            acc.z = fmaf(p0.y, x0.z, acc.z); acc.w = fmaf(p0.y, x0.w, acc.w);
            acc.x = fmaf(p1.y, x1.x, acc.x); acc.y = fmaf(p1.y, x1.y, acc.y);
            acc.z = fmaf(p1.y, x1.z, acc.z); acc.w = fmaf(p1.y, x1.w, acc.w);
            acc.x = fmaf(p2.y, x2.x, acc.x); acc.y = fmaf(p2.y, x2.y, acc.y);
            acc.z = fmaf(p2.y, x2.z, acc.z); acc.w = fmaf(p2.y, x2.w, acc.w);
            acc.x = fmaf(p3.y, x3.x, acc.x); acc.y = fmaf(p3.y, x3.y, acc.y);
            acc.z = fmaf(p3.y, x3.z, acc.z); acc.w = fmaf(p3.y, x3.w, acc.w);
        }
        for (; i < e; i++) {
            float2 p0 = g_csr[i];
            float4 x0 = *(const float4*)(xw + (size_t)__float_as_int(p0.x) * 128 + lane * 4);
            acc.x = fmaf(p0.y, x0.x, acc.x); acc.y = fmaf(p0.y, x0.y, acc.y);
            acc.z = fmaf(p0.y, x0.z, acc.z); acc.w = fmaf(p0.y, x0.w, acc.w);
        }
        float d  = g_deg[warp];
        float d2 = d * d;
        float4 sf = *(const float4*)(xw + (size_t)warp * 128 + lane * 4);
        float4 bb = *(const float4*)(bias + lane * 4);
        float4 r;
        r.x = fmaxf(fmaf(sf.x, d2, acc.x) + bb.x, 0.f);
        r.y = fmaxf(fmaf(sf.y, d2, acc.y) + bb.y, 0.f);
        r.z = fmaxf(fmaf(sf.z, d2, acc.z) + bb.z, 0.f);
        r.w = fmaxf(fmaf(sf.w, d2, acc.w) + bb.w, 0.f);
        *(float4*)(outp + (size_t)warp * 128 + lane * 4) = r;
    } else {
        float2 acc = make_float2(0.f, 0.f);
        int i = s;
        for (; i + 3 < e; i += 4) {
            float2 p0 = g_csr[i],     p1 = g_csr[i + 1];
            float2 p2 = g_csr[i + 2], p3 = g_csr[i + 3];
            float2 x0 = *(const float2*)(xw + (size_t)__float_as_int(p0.x) * 64 + lane * 2);
            float2 x1 = *(const float2*)(xw + (size_t)__float_as_int(p1.x) * 64 + lane * 2);
            float2 x2 = *(const float2*)(xw + (size_t)__float_as_int(p2.x) * 64 + lane * 2);
            float2 x3 = *(const float2*)(xw + (size_t)__float_as_int(p3.x) * 64 + lane * 2);
            acc.x = fmaf(p0.y, x0.x, acc.x); acc.y = fmaf(p0.y, x0.y, acc.y);
            acc.x = fmaf(p1.y, x1.x, acc.x); acc.y = fmaf(p1.y, x1.y, acc.y);
            acc.x = fmaf(p2.y, x2.x, acc.x); acc.y = fmaf(p2.y, x2.y, acc.y);
            acc.x = fmaf(p3.y, x3.x, acc.x); acc.y = fmaf(p3.y, x3.y, acc.y);
        }
        for (; i < e; i++) {
            float2 p0 = g_csr[i];
            float2 x0 = *(const float2*)(xw + (size_t)__float_as_int(p0.x) * 64 + lane * 2);
            acc.x = fmaf(p0.y, x0.x, acc.x); acc.y = fmaf(p0.y, x0.y, acc.y);
        }
        float d  = g_deg[warp];
        float d2 = d * d;
        float2 sf = *(const float2*)(xw + (size_t)warp * 64 + lane * 2);
        float2 bb = *(const float2*)(bias + lane * 2);
        float2 r;
        r.x = fmaxf(fmaf(sf.x, d2, acc.x) + bb.x, 0.f);
        r.y = fmaxf(fmaf(sf.y, d2, acc.y) + bb.y, 0.f);
        *(float2*)(outp + (size_t)warp * 64 + lane * 2) = r;
    }
}

// ---------------------------------------------------------------------------
__global__ void bounds_kernel(const int* __restrict__ batch, int N) {
    int g = threadIdx.x;
    if (g > NGRAPH) return;
    int lo = 0, hi = N;
    while (lo < hi) {
        int mid = (lo + hi) >> 1;
        if (batch[mid] < g) lo = mid + 1; else hi = mid;
    }
    g_gstart[g] = lo;
}

__global__ void pool_kernel() {
    int g = blockIdx.x;
    int t = threadIdx.x;           // 256
    int f   = t & 63;
    int sub = t >> 6;
    int s = g_gstart[g], e = g_gstart[g + 1];
    float acc = 0.0f;
    for (int i = s + sub; i < e; i += 4)
        acc += g_h2[(size_t)i * 64 + f];
    __shared__ float red[256];
    red[t] = acc;
    __syncthreads();
    if (t < 64) {
        float v = red[t] + red[t + 64] + red[t + 128] + red[t + 192];
        float cnt = (float)(e - s);
        g_pool[g * 64 + t] = v / fmaxf(cnt, 1.0f);
    }
}

__global__ void fc_kernel(const float* __restrict__ Wfc,
                          const float* __restrict__ bfc,
                          float* __restrict__ out, int flat) {
    int idx = blockIdx.x * blockDim.x + threadIdx.x;
    int tot = NGRAPH * flat;
    if (idx >= tot) return;
    int g = idx / flat;
    int j = idx - g * flat;
    const float* pg = g_pool + g * 64;
    float s = bfc[j];
    #pragma unroll 8
    for (int k = 0; k < 64; k++)
        s = fmaf(pg[k], Wfc[(size_t)k * flat + j], s);
    out[idx] = s;
}

// ---------------------------------------------------------------------------
// Static stream/event resources (created at load time — NOT during capture)
// ---------------------------------------------------------------------------
static cudaStream_t g_s2;
static cudaEvent_t  g_evFork, g_evJoin;
namespace {
struct StreamInit {
    StreamInit() {
        cudaStreamCreateWithFlags(&g_s2, cudaStreamNonBlocking);
        cudaEventCreateWithFlags(&g_evFork, cudaEventDisableTiming);
        cudaEventCreateWithFlags(&g_evJoin, cudaEventDisableTiming);
    }
};
static StreamInit g_streamInit;
}

// ---------------------------------------------------------------------------
// launch: fork GEMM1+bounds onto stream 2, CSR prologue on default, join.
// ---------------------------------------------------------------------------
extern "C" void kernel_launch(void* const* d_in, const int* in_sizes, int n_in,
                              void* d_out, int out_size) {
    const float* x     = (const float*)d_in[0];
    const int*   ei    = (const int*)d_in[1];
    const float* ew    = (const float*)d_in[2];
    const int*   batch = (const int*)d_in[3];
    const float* W1    = (const float*)d_in[4];
    const float* b1    = (const float*)d_in[5];
    const float* W2    = (const float*)d_in[6];
    const float* b2    = (const float*)d_in[7];
    const float* Wfc   = (const float*)d_in[8];
    const float* bfc   = (const float*)d_in[9];
    float* out = (float*)d_out;

    int N    = in_sizes[0] / 128;   // 40000
    int E    = in_sizes[2];         // 640000
    int flat = in_sizes[8] / 64;    // 2904
    int npart = (N + SCAN_CHUNK - 1) / SCAN_CHUNK;   // 40
    int tb = 256;

    // fork
    cudaEventRecord(g_evFork, 0);
    cudaStreamWaitEvent(g_s2, g_evFork, 0);

    // stream 2: independent of edges — GEMM1 + graph bounds
    bounds_kernel<<<1, 128, 0, g_s2>>>(batch, N);
    sgemm128_kernel<128, 8, -1, BUF_XW1><<<(N + 127) / 128, 256, 0, g_s2>>>(x, W1, N);

    // default stream: CSR prologue
    zero_kernel<<<(N + tb - 1) / tb, tb>>>(N);
    degree_kernel<<<(E + tb - 1) / tb, tb>>>(ei, ew, E);
    scan_part_kernel<<<npart, 256>>>(N);          // fused dis
    scan_spine_kernel<<<1, 32>>>(npart, N, E);
    scan_final_kernel<<<npart, 256>>>(N);
    build_kernel<<<(E + tb - 1) / tb, tb>>>(ei, ew, E);

    // join
    cudaEventRecord(g_evJoin, g_s2);
    cudaStreamWaitEvent(0, g_evJoin, 0);

    // layer 1 aggregate, layer 2, pool, fc
    gather_kernel<128, BUF_XW1, BUF_H1><<<(N + 7) / 8, 256>>>(b1, N);
    sgemm128_kernel<64, 4, BUF_H1, BUF_XW2><<<(N + 127) / 128, 256>>>(nullptr, W2, N);
    gather_kernel<64, BUF_XW2, BUF_H2><<<(N + 7) / 8, 256>>>(b2, N);
    pool_kernel<<<NGRAPH, 256>>>();
    fc_kernel<<<(NGRAPH * flat + tb - 1) / tb, tb>>>(Wfc, bfc, out, flat);
}

// round 8
// speedup vs baseline: 1.2568x; 1.0021x over previous
#include <cuda_runtime.h>
#include <cuda_bf16.h>
#include <mma.h>
#include <math.h>
#include <stdint.h>

using namespace nvcuda;

// ---------------------------------------------------------------------------
// N=40000, E=640000, C_in=128, C_hid=128, C_out=64, G=64, flat=2904.
// edge_index and batch are int32.
// ---------------------------------------------------------------------------
#define MAXN 40000
#define MAXE 640000
#define NGRAPH 64
#define SCAN_CHUNK 1024
#define MAXPART 64

__device__ float  g_deg[MAXN];
__device__ int    g_counts[MAXN];
__device__ int    g_offsets[MAXN + 1];
__device__ int    g_cursor[MAXN];
__device__ int    g_part[MAXPART];
__device__ float2 g_csr[MAXE];
__device__ float  g_xw1[MAXN * 128];
__device__ float  g_h1 [MAXN * 128];
__device__ float  g_xw2[MAXN * 64];
__device__ float  g_h2 [MAXN * 64];
__device__ float  g_pool[NGRAPH * 64];
__device__ int    g_gstart[NGRAPH + 1];

#define BUF_XW1 0
#define BUF_H1  1
#define BUF_XW2 2
#define BUF_H2  3

__device__ __forceinline__ float* buf_ptr(int which) {
    switch (which) {
        case BUF_XW1: return g_xw1;
        case BUF_H1:  return g_h1;
        case BUF_XW2: return g_xw2;
        default:      return g_h2;
    }
}

// ---------------------------------------------------------------------------
// bf16 split helper: v -> (hi, lo) with hi + lo ~ v
// ---------------------------------------------------------------------------
__device__ __forceinline__ void bf16_split(float v, __nv_bfloat16& h, __nv_bfloat16& l) {
    h = __float2bfloat16_rn(v);
    l = __float2bfloat16_rn(v - __bfloat162float(h));
}

// ---------------------------------------------------------------------------
// WMMA GEMM (bf16x3): C[M, N_OUT] = A[M,128] @ W[128, N_OUT]
// 256 threads = 8 warps in 4x2 grid; warp tile 32 x (N_OUT/2).
// SMEM: A_hi | A_lo (128 x 136 bf16 each) | B_hi | B_lo (128 x BSTR bf16 each)
// Last partial tile: stage C in smem (reusing A region), guarded copy out.
// ---------------------------------------------------------------------------
#define ASTR 136
template <int N_OUT, int SRCBUF, int DSTBUF>
__global__ void wmma_gemm_kernel(const float* __restrict__ Ain,
                                 const float* __restrict__ W, int M) {
    constexpr int BSTR = (N_OUT == 128) ? 136 : 72;
    constexpr int NFRAG = N_OUT / 32;          // n-frags per warp (4 or 2)
    constexpr int CSTR = N_OUT + 4;            // staging stride (f32)
    extern __shared__ char smem[];
    __nv_bfloat16* sA_hi = (__nv_bfloat16*)smem;
    __nv_bfloat16* sA_lo = sA_hi + 128 * ASTR;
    __nv_bfloat16* sB_hi = sA_lo + 128 * ASTR;
    __nv_bfloat16* sB_lo = sB_hi + 128 * BSTR;
    float* sC = (float*)smem;                  // reuse A region after mainloop

    const float* __restrict__ A = (SRCBUF >= 0) ? buf_ptr(SRCBUF) : Ain;
    float* __restrict__ C = buf_ptr(DSTBUF);

    int tid = threadIdx.x;
    int row0 = blockIdx.x * 128;

    // fill A tiles (hi/lo), 4 floats per thread-iter
    for (int i = tid; i < 128 * 32; i += 256) {
        int row = i >> 5, q = i & 31;
        float4 v = make_float4(0.f, 0.f, 0.f, 0.f);
        if (row0 + row < M)
            v = *(const float4*)(A + (size_t)(row0 + row) * 128 + q * 4);
        float vv[4] = {v.x, v.y, v.z, v.w};
        __nv_bfloat16 h[4], l[4];
        #pragma unroll
        for (int j = 0; j < 4; j++) bf16_split(vv[j], h[j], l[j]);
        int off = row * ASTR + q * 4;
        *(uint2*)(sA_hi + off) = make_uint2(
            ((uint32_t)__bfloat16_as_ushort(h[1]) << 16) | __bfloat16_as_ushort(h[0]),
            ((uint32_t)__bfloat16_as_ushort(h[3]) << 16) | __bfloat16_as_ushort(h[2]));
        *(uint2*)(sA_lo + off) = make_uint2(
            ((uint32_t)__bfloat16_as_ushort(l[1]) << 16) | __bfloat16_as_ushort(l[0]),
            ((uint32_t)__bfloat16_as_ushort(l[3]) << 16) | __bfloat16_as_ushort(l[2]));
    }
    // fill B tiles (W is [128 k][N_OUT n] row-major)
    for (int i = tid; i < 128 * (N_OUT / 4); i += 256) {
        int k = i / (N_OUT / 4), qc = i % (N_OUT / 4);
        float4 v = *(const float4*)(W + (size_t)k * N_OUT + qc * 4);
        float vv[4] = {v.x, v.y, v.z, v.w};
        __nv_bfloat16 h[4], l[4];
        #pragma unroll
        for (int j = 0; j < 4; j++) bf16_split(vv[j], h[j], l[j]);
        int off = k * BSTR + qc * 4;
        *(uint2*)(sB_hi + off) = make_uint2(
            ((uint32_t)__bfloat16_as_ushort(h[1]) << 16) | __bfloat16_as_ushort(h[0]),
            ((uint32_t)__bfloat16_as_ushort(h[3]) << 16) | __bfloat16_as_ushort(h[2]));
        *(uint2*)(sB_lo + off) = make_uint2(
            ((uint32_t)__bfloat16_as_ushort(l[1]) << 16) | __bfloat16_as_ushort(l[0]),
            ((uint32_t)__bfloat16_as_ushort(l[3]) << 16) | __bfloat16_as_ushort(l[2]));
    }
    __syncthreads();

    int w  = tid >> 5;
    int mw = w & 3;          // 0..3 -> 32-row band
    int nw = w >> 2;         // 0..1 -> (N_OUT/2)-col band
    int colb = nw * (N_OUT / 2);

    wmma::fragment<wmma::accumulator, 16, 16, 16, float> acc[2][NFRAG];
    #pragma unroll
    for (int f = 0; f < 2; f++)
        #pragma unroll
        for (int j = 0; j < NFRAG; j++) wmma::fill_fragment(acc[f][j], 0.0f);

    #pragma unroll
    for (int kk = 0; kk < 8; kk++) {
        wmma::fragment<wmma::matrix_a, 16, 16, 16, __nv_bfloat16, wmma::row_major> ah[2], al[2];
        wmma::fragment<wmma::matrix_b, 16, 16, 16, __nv_bfloat16, wmma::row_major> bh[NFRAG], bl[NFRAG];
        #pragma unroll
        for (int f = 0; f < 2; f++) {
            const __nv_bfloat16* pa = sA_hi + (mw * 32 + f * 16) * ASTR + kk * 16;
            wmma::load_matrix_sync(ah[f], pa, ASTR);
            wmma::load_matrix_sync(al[f], pa + 128 * ASTR, ASTR);
        }
        #pragma unroll
        for (int j = 0; j < NFRAG; j++) {
            const __nv_bfloat16* pb = sB_hi + (kk * 16) * BSTR + colb + j * 16;
            wmma::load_matrix_sync(bh[j], pb, BSTR);
            wmma::load_matrix_sync(bl[j], pb + 128 * BSTR, BSTR);
        }
        #pragma unroll
        for (int f = 0; f < 2; f++)
            #pragma unroll
            for (int j = 0; j < NFRAG; j++) {
                wmma::mma_sync(acc[f][j], ah[f], bh[j], acc[f][j]);
                wmma::mma_sync(acc[f][j], ah[f], bl[j], acc[f][j]);
                wmma::mma_sync(acc[f][j], al[f], bh[j], acc[f][j]);
            }
    }

    if (row0 + 128 <= M) {
        // full tile: store straight to global
        #pragma unroll
        for (int f = 0; f < 2; f++)
            #pragma unroll
            for (int j = 0; j < NFRAG; j++)
                wmma::store_matrix_sync(
                    C + (size_t)(row0 + mw * 32 + f * 16) * N_OUT + colb + j * 16,
                    acc[f][j], N_OUT, wmma::mem_row_major);
    } else {
        // partial tile: stage in smem, guarded copy
        __syncthreads();
        #pragma unroll
        for (int f = 0; f < 2; f++)
            #pragma unroll
            for (int j = 0; j < NFRAG; j++)
                wmma::store_matrix_sync(
                    sC + (size_t)(mw * 32 + f * 16) * CSTR + colb + j * 16,
                    acc[f][j], CSTR, wmma::mem_row_major);
        __syncthreads();
        for (int i = tid; i < 128 * (N_OUT / 4); i += 256) {
            int row = i / (N_OUT / 4), qc = i % (N_OUT / 4);
            if (row0 + row < M) {
                float4 v = *(float4*)(sC + (size_t)row * CSTR + qc * 4);
                *(float4*)(C + (size_t)(row0 + row) * N_OUT + qc * 4) = v;
            }
        }
    }
}
#define WMMA_SMEM_128 (4 * 128 * 136 * 2)            /* 139264 */
#define WMMA_SMEM_64  (2 * 128 * 136 * 2 + 2 * 128 * 72 * 2)

// ---------------------------------------------------------------------------
__global__ void zero_kernel(int n) {
    int i = blockIdx.x * blockDim.x + threadIdx.x;
    if (i < n) { g_deg[i] = 0.0f; g_counts[i] = 0; }
}

__global__ void degree_kernel(const int* __restrict__ ei,
                              const float* __restrict__ ew, int E) {
    int e = blockIdx.x * blockDim.x + threadIdx.x;
    if (e >= E) return;
    int col = ei[E + e];
    atomicAdd(&g_deg[col], ew[e]);
    atomicAdd(&g_counts[col], 1);
}

__global__ void scan_part_kernel(int n) {
    __shared__ int warp_sums[8];
    int t = threadIdx.x;
    int base = blockIdx.x * SCAN_CHUNK;
    int s = 0;
    #pragma unroll
    for (int j = 0; j < 4; j++) {
        int idx = base + t * 4 + j;
        if (idx < n) {
            s += g_counts[idx];
            g_deg[idx] = rsqrtf(g_deg[idx] + 1.0f);
        }
    }
    #pragma unroll
    for (int o = 16; o > 0; o >>= 1) s += __shfl_down_sync(0xFFFFFFFFu, s, o);
    if ((t & 31) == 0) warp_sums[t >> 5] = s;
    __syncthreads();
    if (t < 8) {
        int v = warp_sums[t];
        #pragma unroll
        for (int o = 4; o > 0; o >>= 1) v += __shfl_down_sync(0xFFu, v, o);
        if (t == 0) g_part[blockIdx.x] = v;
    }
}

__global__ void scan_spine_kernel(int npart, int n, int E) {
    int lane = threadIdx.x;
    int a = (lane * 2     < npart) ? g_part[lane * 2]     : 0;
    int b = (lane * 2 + 1 < npart) ? g_part[lane * 2 + 1] : 0;
    int s = a + b;
    int x = s;
    #pragma unroll
    for (int o = 1; o < 32; o <<= 1) {
        int y = __shfl_up_sync(0xFFFFFFFFu, x, o);
        if (lane >= o) x += y;
    }
    int excl = x - s;
    if (lane * 2     < npart) g_part[lane * 2]     = excl;
    if (lane * 2 + 1 < npart) g_part[lane * 2 + 1] = excl + a;
    if (lane == 0) g_offsets[n] = E;
}

__global__ void scan_final_kernel(int n) {
    __shared__ int warp_sums[8];
    int t = threadIdx.x, lane = t & 31, wid = t >> 5;
    int base = blockIdx.x * SCAN_CHUNK;
    int v[4], p = 0;
    #pragma unroll
    for (int j = 0; j < 4; j++) {
        int idx = base + t * 4 + j;
        v[j] = (idx < n) ? g_counts[idx] : 0;
        p += v[j];
    }
    int x = p;
    #pragma unroll
    for (int o = 1; o < 32; o <<= 1) {
        int y = __shfl_up_sync(0xFFFFFFFFu, x, o);
        if (lane >= o) x += y;
    }
    if (lane == 31) warp_sums[wid] = x;
    __syncthreads();
    if (t < 8) {
        int s = warp_sums[t];
        #pragma unroll
        for (int o = 1; o < 8; o <<= 1) {
            int y = __shfl_up_sync(0xFFu, s, o);
            if (t >= o) s += y;
        }
        warp_sums[t] = s;
    }
    __syncthreads();
    int bexcl = g_part[blockIdx.x] + ((wid > 0) ? warp_sums[wid - 1] : 0) + (x - p);
    #pragma unroll
    for (int j = 0; j < 4; j++) {
        int idx = base + t * 4 + j;
        if (idx < n) { g_offsets[idx] = bexcl; g_cursor[idx] = bexcl; }
        bexcl += v[j];
    }
}

__global__ void build_kernel(const int* __restrict__ ei,
                             const float* __restrict__ ew, int E) {
    int e = blockIdx.x * blockDim.x + threadIdx.x;
    if (e >= E) return;
    int row = ei[e];
    int col = ei[E + e];
    int slot = atomicAdd(&g_cursor[col], 1);
    float w = g_deg[row] * ew[e] * g_deg[col];
    g_csr[slot] = make_float2(__int_as_float(row), w);
}

// ---------------------------------------------------------------------------
// Gather + self-loop + bias + ReLU. One warp per node, unroll 4.
// ---------------------------------------------------------------------------
template <int F, int SRCBUF, int DSTBUF>
__global__ void gather_kernel(const float* __restrict__ bias, int Nn) {
    const float* __restrict__ xw = buf_ptr(SRCBUF);
    float* __restrict__ outp = buf_ptr(DSTBUF);
    int warp = (blockIdx.x * blockDim.x + threadIdx.x) >> 5;
    int lane = threadIdx.x & 31;
    if (warp >= Nn) return;
    int s = g_offsets[warp];
    int e = g_offsets[warp + 1];

    if (F == 128) {
        float4 acc = make_float4(0.f, 0.f, 0.f, 0.f);
        int i = s;
        for (; i + 3 < e; i += 4) {
            float2 p0 = g_csr[i],     p1 = g_csr[i + 1];
            float2 p2 = g_csr[i + 2], p3 = g_csr[i + 3];
            float4 x0 = *(const float4*)(xw + (size_t)__float_as_int(p0.x) * 128 + lane * 4);
            float4 x1 = *(const float4*)(xw + (size_t)__float_as_int(p1.x) * 128 + lane * 4);
            float4 x2 = *(const float4*)(xw + (size_t)__float_as_int(p2.x) * 128 + lane * 4);
            float4 x3 = *(const float4*)(xw + (size_t)__float_as_int(p3.x) * 128 + lane * 4);
            acc.x = fmaf(p0.y, x0.x, acc.x); acc.y = fmaf(p0.y, x0.y, acc.y);
            acc.z = fmaf(p0.y, x0.z, acc.z); acc.w = fmaf(p0.y, x0.w, acc.w);
            acc.x = fmaf(p1.y, x1.x, acc.x); acc.y = fmaf(p1.y, x1.y, acc.y);
            acc.z = fmaf(p1.y, x1.z, acc.z); acc.w = fmaf(p1.y, x1.w, acc.w);
            acc.x = fmaf(p2.y, x2.x, acc.x); acc.y = fmaf(p2.y, x2.y, acc.y);
            acc.z = fmaf(p2.y, x2.z, acc.z); acc.w = fmaf(p2.y, x2.w, acc.w);
            acc.x = fmaf(p3.y, x3.x, acc.x); acc.y = fmaf(p3.y, x3.y, acc.y);
            acc.z = fmaf(p3.y, x3.z, acc.z); acc.w = fmaf(p3.y, x3.w, acc.w);
        }
        for (; i < e; i++) {
            float2 p0 = g_csr[i];
            float4 x0 = *(const float4*)(xw + (size_t)__float_as_int(p0.x) * 128 + lane * 4);
            acc.x = fmaf(p0.y, x0.x, acc.x); acc.y = fmaf(p0.y, x0.y, acc.y);
            acc.z = fmaf(p0.y, x0.z, acc.z); acc.w = fmaf(p0.y, x0.w, acc.w);
        }
        float d  = g_deg[warp];
        float d2 = d * d;
        float4 sf = *(const float4*)(xw + (size_t)warp * 128 + lane * 4);
        float4 bb = *(const float4*)(bias + lane * 4);
        float4 r;
        r.x = fmaxf(fmaf(sf.x, d2, acc.x) + bb.x, 0.f);
        r.y = fmaxf(fmaf(sf.y, d2, acc.y) + bb.y, 0.f);
        r.z = fmaxf(fmaf(sf.z, d2, acc.z) + bb.z, 0.f);
        r.w = fmaxf(fmaf(sf.w, d2, acc.w) + bb.w, 0.f);
        *(float4*)(outp + (size_t)warp * 128 + lane * 4) = r;
    } else {
        float2 acc = make_float2(0.f, 0.f);
        int i = s;
        for (; i + 3 < e; i += 4) {
            float2 p0 = g_csr[i],     p1 = g_csr[i + 1];
            float2 p2 = g_csr[i + 2], p3 = g_csr[i + 3];
            float2 x0 = *(const float2*)(xw + (size_t)__float_as_int(p0.x) * 64 + lane * 2);
            float2 x1 = *(const float2*)(xw + (size_t)__float_as_int(p1.x) * 64 + lane * 2);
            float2 x2 = *(const float2*)(xw + (size_t)__float_as_int(p2.x) * 64 + lane * 2);
            float2 x3 = *(const float2*)(xw + (size_t)__float_as_int(p3.x) * 64 + lane * 2);
            acc.x = fmaf(p0.y, x0.x, acc.x); acc.y = fmaf(p0.y, x0.y, acc.y);
            acc.x = fmaf(p1.y, x1.x, acc.x); acc.y = fmaf(p1.y, x1.y, acc.y);
            acc.x = fmaf(p2.y, x2.x, acc.x); acc.y = fmaf(p2.y, x2.y, acc.y);
            acc.x = fmaf(p3.y, x3.x, acc.x); acc.y = fmaf(p3.y, x3.y, acc.y);
        }
        for (; i < e; i++) {
            float2 p0 = g_csr[i];
            float2 x0 = *(const float2*)(xw + (size_t)__float_as_int(p0.x) * 64 + lane * 2);
            acc.x = fmaf(p0.y, x0.x, acc.x); acc.y = fmaf(p0.y, x0.y, acc.y);
        }
        float d  = g_deg[warp];
        float d2 = d * d;
        float2 sf = *(const float2*)(xw + (size_t)warp * 64 + lane * 2);
        float2 bb = *(const float2*)(bias + lane * 2);
        float2 r;
        r.x = fmaxf(fmaf(sf.x, d2, acc.x) + bb.x, 0.f);
        r.y = fmaxf(fmaf(sf.y, d2, acc.y) + bb.y, 0.f);
        *(float2*)(outp + (size_t)warp * 64 + lane * 2) = r;
    }
}

// ---------------------------------------------------------------------------
__global__ void bounds_kernel(const int* __restrict__ batch, int N) {
    int g = threadIdx.x;
    if (g > NGRAPH) return;
    int lo = 0, hi = N;
    while (lo < hi) {
        int mid = (lo + hi) >> 1;
        if (batch[mid] < g) lo = mid + 1; else hi = mid;
    }
    g_gstart[g] = lo;
}

__global__ void pool_kernel() {
    int g = blockIdx.x;
    int t = threadIdx.x;
    int f   = t & 63;
    int sub = t >> 6;
    int s = g_gstart[g], e = g_gstart[g + 1];
    float acc = 0.0f;
    for (int i = s + sub; i < e; i += 4)
        acc += g_h2[(size_t)i * 64 + f];
    __shared__ float red[256];
    red[t] = acc;
    __syncthreads();
    if (t < 64) {
        float v = red[t] + red[t + 64] + red[t + 128] + red[t + 192];
        float cnt = (float)(e - s);
        g_pool[g * 64 + t] = v / fmaxf(cnt, 1.0f);
    }
}

__global__ void fc_kernel(const float* __restrict__ Wfc,
                          const float* __restrict__ bfc,
                          float* __restrict__ out, int flat) {
    int idx = blockIdx.x * blockDim.x + threadIdx.x;
    int tot = NGRAPH * flat;
    if (idx >= tot) return;
    int g = idx / flat;
    int j = idx - g * flat;
    const float* pg = g_pool + g * 64;
    float s = bfc[j];
    #pragma unroll 8
    for (int k = 0; k < 64; k++)
        s = fmaf(pg[k], Wfc[(size_t)k * flat + j], s);
    out[idx] = s;
}

// ---------------------------------------------------------------------------
// Static resources (created at load time — NOT during capture)
// ---------------------------------------------------------------------------
static cudaStream_t g_s2;
static cudaEvent_t  g_evFork, g_evJoin;
namespace {
struct StreamInit {
    StreamInit() {
        cudaStreamCreateWithFlags(&g_s2, cudaStreamNonBlocking);
        cudaEventCreateWithFlags(&g_evFork, cudaEventDisableTiming);
        cudaEventCreateWithFlags(&g_evJoin, cudaEventDisableTiming);
        cudaFuncSetAttribute(wmma_gemm_kernel<128, -1, BUF_XW1>,
                             cudaFuncAttributeMaxDynamicSharedMemorySize, WMMA_SMEM_128);
        cudaFuncSetAttribute(wmma_gemm_kernel<64, BUF_H1, BUF_XW2>,
                             cudaFuncAttributeMaxDynamicSharedMemorySize, WMMA_SMEM_64);
    }
};
static StreamInit g_streamInit;
}

// ---------------------------------------------------------------------------
extern "C" void kernel_launch(void* const* d_in, const int* in_sizes, int n_in,
                              void* d_out, int out_size) {
    const float* x     = (const float*)d_in[0];
    const int*   ei    = (const int*)d_in[1];
    const float* ew    = (const float*)d_in[2];
    const int*   batch = (const int*)d_in[3];
    const float* W1    = (const float*)d_in[4];
    const float* b1    = (const float*)d_in[5];
    const float* W2    = (const float*)d_in[6];
    const float* b2    = (const float*)d_in[7];
    const float* Wfc   = (const float*)d_in[8];
    const float* bfc   = (const float*)d_in[9];
    float* out = (float*)d_out;

    int N    = in_sizes[0] / 128;   // 40000
    int E    = in_sizes[2];         // 640000
    int flat = in_sizes[8] / 64;    // 2904
    int npart = (N + SCAN_CHUNK - 1) / SCAN_CHUNK;
    int tb = 256;
    int ngrid = (N + 127) / 128;    // 313

    // fork
    cudaEventRecord(g_evFork, 0);
    cudaStreamWaitEvent(g_s2, g_evFork, 0);

    // stream 2: independent of edges — GEMM1 + graph bounds
    bounds_kernel<<<1, 128, 0, g_s2>>>(batch, N);
    wmma_gemm_kernel<128, -1, BUF_XW1><<<ngrid, 256, WMMA_SMEM_128, g_s2>>>(x, W1, N);

    // default stream: CSR prologue
    zero_kernel<<<(N + tb - 1) / tb, tb>>>(N);
    degree_kernel<<<(E + tb - 1) / tb, tb>>>(ei, ew, E);
    scan_part_kernel<<<npart, 256>>>(N);
    scan_spine_kernel<<<1, 32>>>(npart, N, E);
    scan_final_kernel<<<npart, 256>>>(N);
    build_kernel<<<(E + tb - 1) / tb, tb>>>(ei, ew, E);

    // join
    cudaEventRecord(g_evJoin, g_s2);
    cudaStreamWaitEvent(0, g_evJoin, 0);

    // layer 1 aggregate, layer 2, pool, fc
    gather_kernel<128, BUF_XW1, BUF_H1><<<(N + 7) / 8, 256>>>(b1, N);
    wmma_gemm_kernel<64, BUF_H1, BUF_XW2><<<ngrid, 256, WMMA_SMEM_64>>>(nullptr, W2, N);
    gather_kernel<64, BUF_XW2, BUF_H2><<<(N + 7) / 8, 256>>>(b2, N);
    pool_kernel<<<NGRAPH, 256>>>();
    fc_kernel<<<(NGRAPH * flat + tb - 1) / tb, tb>>>(Wfc, bfc, out, flat);
}

// round 9
// speedup vs baseline: 1.2726x; 1.0126x over previous
#include <cuda_runtime.h>
#include <cuda_bf16.h>
#include <mma.h>
#include <math.h>
#include <stdint.h>

using namespace nvcuda;

// ---------------------------------------------------------------------------
// N=40000, E=640000, C_in=128, C_hid=128, C_out=64, G=64, flat=2904.
// edge_index and batch are int32.
// ---------------------------------------------------------------------------
#define MAXN 40000
#define MAXE 640000
#define NGRAPH 64
#define SCAN_CHUNK 1024
#define MAXPART 64

__device__ float  g_deg[MAXN];
__device__ int    g_counts[MAXN];
__device__ int    g_offsets[MAXN + 1];
__device__ int    g_cursor[MAXN];
__device__ int    g_part[MAXPART];
__device__ float2 g_csr[MAXE];
__device__ float  g_xw1[MAXN * 128];
__device__ float  g_h1 [MAXN * 128];
__device__ float  g_xw2[MAXN * 64];
__device__ float  g_h2 [MAXN * 64];
__device__ float  g_pool[NGRAPH * 64];

#define BUF_XW1 0
#define BUF_H1  1
#define BUF_XW2 2
#define BUF_H2  3

__device__ __forceinline__ float* buf_ptr(int which) {
    switch (which) {
        case BUF_XW1: return g_xw1;
        case BUF_H1:  return g_h1;
        case BUF_XW2: return g_xw2;
        default:      return g_h2;
    }
}

__device__ __forceinline__ void bf16_split(float v, __nv_bfloat16& h, __nv_bfloat16& l) {
    h = __float2bfloat16_rn(v);
    l = __float2bfloat16_rn(v - __bfloat162float(h));
}

// ---------------------------------------------------------------------------
// WMMA GEMM (bf16x3): C[rows base..base+grid*128, N_OUT] = A[.,128] @ W[128, N_OUT]
// ---------------------------------------------------------------------------
#define ASTR 136
template <int N_OUT, int SRCBUF, int DSTBUF>
__global__ void wmma_gemm_kernel(const float* __restrict__ Ain,
                                 const float* __restrict__ W, int M, int base) {
    constexpr int BSTR = (N_OUT == 128) ? 136 : 72;
    constexpr int NFRAG = N_OUT / 32;
    constexpr int CSTR = N_OUT + 4;
    extern __shared__ char smem[];
    __nv_bfloat16* sA_hi = (__nv_bfloat16*)smem;
    __nv_bfloat16* sA_lo = sA_hi + 128 * ASTR;
    __nv_bfloat16* sB_hi = sA_lo + 128 * ASTR;
    __nv_bfloat16* sB_lo = sB_hi + 128 * BSTR;
    float* sC = (float*)smem;

    const float* __restrict__ A = (SRCBUF >= 0) ? buf_ptr(SRCBUF) : Ain;
    float* __restrict__ C = buf_ptr(DSTBUF);

    int tid = threadIdx.x;
    int row0 = base + blockIdx.x * 128;

    for (int i = tid; i < 128 * 32; i += 256) {
        int row = i >> 5, q = i & 31;
        float4 v = make_float4(0.f, 0.f, 0.f, 0.f);
        if (row0 + row < M)
            v = *(const float4*)(A + (size_t)(row0 + row) * 128 + q * 4);
        float vv[4] = {v.x, v.y, v.z, v.w};
        __nv_bfloat16 h[4], l[4];
        #pragma unroll
        for (int j = 0; j < 4; j++) bf16_split(vv[j], h[j], l[j]);
        int off = row * ASTR + q * 4;
        *(uint2*)(sA_hi + off) = make_uint2(
            ((uint32_t)__bfloat16_as_ushort(h[1]) << 16) | __bfloat16_as_ushort(h[0]),
            ((uint32_t)__bfloat16_as_ushort(h[3]) << 16) | __bfloat16_as_ushort(h[2]));
        *(uint2*)(sA_lo + off) = make_uint2(
            ((uint32_t)__bfloat16_as_ushort(l[1]) << 16) | __bfloat16_as_ushort(l[0]),
            ((uint32_t)__bfloat16_as_ushort(l[3]) << 16) | __bfloat16_as_ushort(l[2]));
    }
    for (int i = tid; i < 128 * (N_OUT / 4); i += 256) {
        int k = i / (N_OUT / 4), qc = i % (N_OUT / 4);
        float4 v = *(const float4*)(W + (size_t)k * N_OUT + qc * 4);
        float vv[4] = {v.x, v.y, v.z, v.w};
        __nv_bfloat16 h[4], l[4];
        #pragma unroll
        for (int j = 0; j < 4; j++) bf16_split(vv[j], h[j], l[j]);
        int off = k * BSTR + qc * 4;
        *(uint2*)(sB_hi + off) = make_uint2(
            ((uint32_t)__bfloat16_as_ushort(h[1]) << 16) | __bfloat16_as_ushort(h[0]),
            ((uint32_t)__bfloat16_as_ushort(h[3]) << 16) | __bfloat16_as_ushort(h[2]));
        *(uint2*)(sB_lo + off) = make_uint2(
            ((uint32_t)__bfloat16_as_ushort(l[1]) << 16) | __bfloat16_as_ushort(l[0]),
            ((uint32_t)__bfloat16_as_ushort(l[3]) << 16) | __bfloat16_as_ushort(l[2]));
    }
    __syncthreads();

    int w  = tid >> 5;
    int mw = w & 3;
    int nw = w >> 2;
    int colb = nw * (N_OUT / 2);

    wmma::fragment<wmma::accumulator, 16, 16, 16, float> acc[2][NFRAG];
    #pragma unroll
    for (int f = 0; f < 2; f++)
        #pragma unroll
        for (int j = 0; j < NFRAG; j++) wmma::fill_fragment(acc[f][j], 0.0f);

    #pragma unroll
    for (int kk = 0; kk < 8; kk++) {
        wmma::fragment<wmma::matrix_a, 16, 16, 16, __nv_bfloat16, wmma::row_major> ah[2], al[2];
        wmma::fragment<wmma::matrix_b, 16, 16, 16, __nv_bfloat16, wmma::row_major> bh[NFRAG], bl[NFRAG];
        #pragma unroll
        for (int f = 0; f < 2; f++) {
            const __nv_bfloat16* pa = sA_hi + (mw * 32 + f * 16) * ASTR + kk * 16;
            wmma::load_matrix_sync(ah[f], pa, ASTR);
            wmma::load_matrix_sync(al[f], pa + 128 * ASTR, ASTR);
        }
        #pragma unroll
        for (int j = 0; j < NFRAG; j++) {
            const __nv_bfloat16* pb = sB_hi + (kk * 16) * BSTR + colb + j * 16;
            wmma::load_matrix_sync(bh[j], pb, BSTR);
            wmma::load_matrix_sync(bl[j], pb + 128 * BSTR, BSTR);
        }
        #pragma unroll
        for (int f = 0; f < 2; f++)
            #pragma unroll
            for (int j = 0; j < NFRAG; j++) {
                wmma::mma_sync(acc[f][j], ah[f], bh[j], acc[f][j]);
                wmma::mma_sync(acc[f][j], ah[f], bl[j], acc[f][j]);
                wmma::mma_sync(acc[f][j], al[f], bh[j], acc[f][j]);
            }
    }

    if (row0 + 128 <= M) {
        #pragma unroll
        for (int f = 0; f < 2; f++)
            #pragma unroll
            for (int j = 0; j < NFRAG; j++)
                wmma::store_matrix_sync(
                    C + (size_t)(row0 + mw * 32 + f * 16) * N_OUT + colb + j * 16,
                    acc[f][j], N_OUT, wmma::mem_row_major);
    } else {
        __syncthreads();
        #pragma unroll
        for (int f = 0; f < 2; f++)
            #pragma unroll
            for (int j = 0; j < NFRAG; j++)
                wmma::store_matrix_sync(
                    sC + (size_t)(mw * 32 + f * 16) * CSTR + colb + j * 16,
                    acc[f][j], CSTR, wmma::mem_row_major);
        __syncthreads();
        for (int i = tid; i < 128 * (N_OUT / 4); i += 256) {
            int row = i / (N_OUT / 4), qc = i % (N_OUT / 4);
            if (row0 + row < M) {
                float4 v = *(float4*)(sC + (size_t)row * CSTR + qc * 4);
                *(float4*)(C + (size_t)(row0 + row) * N_OUT + qc * 4) = v;
            }
        }
    }
}
#define WMMA_SMEM_128 (4 * 128 * 136 * 2)
#define WMMA_SMEM_64  (2 * 128 * 136 * 2 + 2 * 128 * 72 * 2)

// ---------------------------------------------------------------------------
__global__ void zero_kernel(int n) {
    int i = blockIdx.x * blockDim.x + threadIdx.x;
    if (i < n) { g_deg[i] = 0.0f; g_counts[i] = 0; }
}

__global__ void degree_kernel(const int* __restrict__ ei,
                              const float* __restrict__ ew, int E) {
    int e = blockIdx.x * blockDim.x + threadIdx.x;
    if (e >= E) return;
    int col = ei[E + e];
    atomicAdd(&g_deg[col], ew[e]);
    atomicAdd(&g_counts[col], 1);
}

__global__ void scan_part_kernel(int n) {
    __shared__ int warp_sums[8];
    int t = threadIdx.x;
    int base = blockIdx.x * SCAN_CHUNK;
    int s = 0;
    #pragma unroll
    for (int j = 0; j < 4; j++) {
        int idx = base + t * 4 + j;
        if (idx < n) {
            s += g_counts[idx];
            g_deg[idx] = rsqrtf(g_deg[idx] + 1.0f);
        }
    }
    #pragma unroll
    for (int o = 16; o > 0; o >>= 1) s += __shfl_down_sync(0xFFFFFFFFu, s, o);
    if ((t & 31) == 0) warp_sums[t >> 5] = s;
    __syncthreads();
    if (t < 8) {
        int v = warp_sums[t];
        #pragma unroll
        for (int o = 4; o > 0; o >>= 1) v += __shfl_down_sync(0xFFu, v, o);
        if (t == 0) g_part[blockIdx.x] = v;
    }
}

// final scan: every block redundantly scans the (<=64) partials inline (spine
// kernel eliminated), then scans its own chunk and writes offsets + cursor.
__global__ void scan_final_kernel(int npart, int n, int E) {
    __shared__ int warp_sums[8];
    __shared__ int spine[MAXPART];
    int t = threadIdx.x, lane = t & 31, wid = t >> 5;

    if (t < 32) {                       // warp 0: exclusive scan of partials
        int a = (t * 2     < npart) ? g_part[t * 2]     : 0;
        int b = (t * 2 + 1 < npart) ? g_part[t * 2 + 1] : 0;
        int s = a + b;
        int x = s;
        #pragma unroll
        for (int o = 1; o < 32; o <<= 1) {
            int y = __shfl_up_sync(0xFFFFFFFFu, x, o);
            if (t >= o) x += y;
        }
        int excl = x - s;
        spine[t * 2]     = excl;
        spine[t * 2 + 1] = excl + a;
    }
    __syncthreads();

    int base = blockIdx.x * SCAN_CHUNK;
    int v[4], p = 0;
    #pragma unroll
    for (int j = 0; j < 4; j++) {
        int idx = base + t * 4 + j;
        v[j] = (idx < n) ? g_counts[idx] : 0;
        p += v[j];
    }
    int x = p;
    #pragma unroll
    for (int o = 1; o < 32; o <<= 1) {
        int y = __shfl_up_sync(0xFFFFFFFFu, x, o);
        if (lane >= o) x += y;
    }
    if (lane == 31) warp_sums[wid] = x;
    __syncthreads();
    if (t < 8) {
        int s = warp_sums[t];
        #pragma unroll
        for (int o = 1; o < 8; o <<= 1) {
            int y = __shfl_up_sync(0xFFu, s, o);
            if (t >= o) s += y;
        }
        warp_sums[t] = s;
    }
    __syncthreads();
    int bexcl = spine[blockIdx.x] + ((wid > 0) ? warp_sums[wid - 1] : 0) + (x - p);
    #pragma unroll
    for (int j = 0; j < 4; j++) {
        int idx = base + t * 4 + j;
        if (idx < n) { g_offsets[idx] = bexcl; g_cursor[idx] = bexcl; }
        bexcl += v[j];
    }
    if (blockIdx.x == 0 && t == 0) g_offsets[n] = E;
}

__global__ void build_kernel(const int* __restrict__ ei,
                             const float* __restrict__ ew, int E) {
    int e = blockIdx.x * blockDim.x + threadIdx.x;
    if (e >= E) return;
    int row = ei[e];
    int col = ei[E + e];
    int slot = atomicAdd(&g_cursor[col], 1);
    float w = g_deg[row] * ew[e] * g_deg[col];
    g_csr[slot] = make_float2(__int_as_float(row), w);
}

// ---------------------------------------------------------------------------
// Gather + self-loop + bias + ReLU. One warp per node in [base, base+count).
// ---------------------------------------------------------------------------
template <int F, int SRCBUF, int DSTBUF>
__global__ void gather_kernel(const float* __restrict__ bias, int base, int count, int M) {
    const float* __restrict__ xw = buf_ptr(SRCBUF);
    float* __restrict__ outp = buf_ptr(DSTBUF);
    int gid = (blockIdx.x * blockDim.x + threadIdx.x) >> 5;
    int lane = threadIdx.x & 31;
    if (gid >= count) return;
    int warp = base + gid;
    if (warp >= M) return;
    int s = g_offsets[warp];
    int e = g_offsets[warp + 1];

    if (F == 128) {
        float4 acc = make_float4(0.f, 0.f, 0.f, 0.f);
        int i = s;
        for (; i + 3 < e; i += 4) {
            float2 p0 = g_csr[i],     p1 = g_csr[i + 1];
            float2 p2 = g_csr[i + 2], p3 = g_csr[i + 3];
            float4 x0 = *(const float4*)(xw + (size_t)__float_as_int(p0.x) * 128 + lane * 4);
            float4 x1 = *(const float4*)(xw + (size_t)__float_as_int(p1.x) * 128 + lane * 4);
            float4 x2 = *(const float4*)(xw + (size_t)__float_as_int(p2.x) * 128 + lane * 4);
            float4 x3 = *(const float4*)(xw + (size_t)__float_as_int(p3.x) * 128 + lane * 4);
            acc.x = fmaf(p0.y, x0.x, acc.x); acc.y = fmaf(p0.y, x0.y, acc.y);
            acc.z = fmaf(p0.y, x0.z, acc.z); acc.w = fmaf(p0.y, x0.w, acc.w);
            acc.x = fmaf(p1.y, x1.x, acc.x); acc.y = fmaf(p1.y, x1.y, acc.y);
            acc.z = fmaf(p1.y, x1.z, acc.z); acc.w = fmaf(p1.y, x1.w, acc.w);
            acc.x = fmaf(p2.y, x2.x, acc.x); acc.y = fmaf(p2.y, x2.y, acc.y);
            acc.z = fmaf(p2.y, x2.z, acc.z); acc.w = fmaf(p2.y, x2.w, acc.w);
            acc.x = fmaf(p3.y, x3.x, acc.x); acc.y = fmaf(p3.y, x3.y, acc.y);
            acc.z = fmaf(p3.y, x3.z, acc.z); acc.w = fmaf(p3.y, x3.w, acc.w);
        }
        for (; i < e; i++) {
            float2 p0 = g_csr[i];
            float4 x0 = *(const float4*)(xw + (size_t)__float_as_int(p0.x) * 128 + lane * 4);
            acc.x = fmaf(p0.y, x0.x, acc.x); acc.y = fmaf(p0.y, x0.y, acc.y);
            acc.z = fmaf(p0.y, x0.z, acc.z); acc.w = fmaf(p0.y, x0.w, acc.w);
        }
        float d  = g_deg[warp];
        float d2 = d * d;
        float4 sf = *(const float4*)(xw + (size_t)warp * 128 + lane * 4);
        float4 bb = *(const float4*)(bias + lane * 4);
        float4 r;
        r.x = fmaxf(fmaf(sf.x, d2, acc.x) + bb.x, 0.f);
        r.y = fmaxf(fmaf(sf.y, d2, acc.y) + bb.y, 0.f);
        r.z = fmaxf(fmaf(sf.z, d2, acc.z) + bb.z, 0.f);
        r.w = fmaxf(fmaf(sf.w, d2, acc.w) + bb.w, 0.f);
        *(float4*)(outp + (size_t)warp * 128 + lane * 4) = r;
    } else {
        float2 acc = make_float2(0.f, 0.f);
        int i = s;
        for (; i + 3 < e; i += 4) {
            float2 p0 = g_csr[i],     p1 = g_csr[i + 1];
            float2 p2 = g_csr[i + 2], p3 = g_csr[i + 3];
            float2 x0 = *(const float2*)(xw + (size_t)__float_as_int(p0.x) * 64 + lane * 2);
            float2 x1 = *(const float2*)(xw + (size_t)__float_as_int(p1.x) * 64 + lane * 2);
            float2 x2 = *(const float2*)(xw + (size_t)__float_as_int(p2.x) * 64 + lane * 2);
            float2 x3 = *(const float2*)(xw + (size_t)__float_as_int(p3.x) * 64 + lane * 2);
            acc.x = fmaf(p0.y, x0.x, acc.x); acc.y = fmaf(p0.y, x0.y, acc.y);
            acc.x = fmaf(p1.y, x1.x, acc.x); acc.y = fmaf(p1.y, x1.y, acc.y);
            acc.x = fmaf(p2.y, x2.x, acc.x); acc.y = fmaf(p2.y, x2.y, acc.y);
            acc.x = fmaf(p3.y, x3.x, acc.x); acc.y = fmaf(p3.y, x3.y, acc.y);
        }
        for (; i < e; i++) {
            float2 p0 = g_csr[i];
            float2 x0 = *(const float2*)(xw + (size_t)__float_as_int(p0.x) * 64 + lane * 2);
            acc.x = fmaf(p0.y, x0.x, acc.x); acc.y = fmaf(p0.y, x0.y, acc.y);
        }
        float d  = g_deg[warp];
        float d2 = d * d;
        float2 sf = *(const float2*)(xw + (size_t)warp * 64 + lane * 2);
        float2 bb = *(const float2*)(bias + lane * 2);
        float2 r;
        r.x = fmaxf(fmaf(sf.x, d2, acc.x) + bb.x, 0.f);
        r.y = fmaxf(fmaf(sf.y, d2, acc.y) + bb.y, 0.f);
        *(float2*)(outp + (size_t)warp * 64 + lane * 2) = r;
    }
}

// ---------------------------------------------------------------------------
// pool with inlined per-graph bounds (binary search on sorted batch)
// ---------------------------------------------------------------------------
__global__ void pool_kernel(const int* __restrict__ batch, int N) {
    int g = blockIdx.x;
    int t = threadIdx.x;
    __shared__ int bnd[2];
    if (t < 2) {
        int target = g + t;
        int lo = 0, hi = N;
        while (lo < hi) {
            int mid = (lo + hi) >> 1;
            if (batch[mid] < target) lo = mid + 1; else hi = mid;
        }
        bnd[t] = lo;
    }
    __syncthreads();
    int s = bnd[0], e = bnd[1];
    int f   = t & 63;
    int sub = t >> 6;
    float acc = 0.0f;
    for (int i = s + sub; i < e; i += 4)
        acc += g_h2[(size_t)i * 64 + f];
    __shared__ float red[256];
    red[t] = acc;
    __syncthreads();
    if (t < 64) {
        float v = red[t] + red[t + 64] + red[t + 128] + red[t + 192];
        float cnt = (float)(e - s);
        g_pool[g * 64 + t] = v / fmaxf(cnt, 1.0f);
    }
}

__global__ void fc_kernel(const float* __restrict__ Wfc,
                          const float* __restrict__ bfc,
                          float* __restrict__ out, int flat) {
    int idx = blockIdx.x * blockDim.x + threadIdx.x;
    int tot = NGRAPH * flat;
    if (idx >= tot) return;
    int g = idx / flat;
    int j = idx - g * flat;
    const float* pg = g_pool + g * 64;
    float s = bfc[j];
    #pragma unroll 8
    for (int k = 0; k < 64; k++)
        s = fmaf(pg[k], Wfc[(size_t)k * flat + j], s);
    out[idx] = s;
}

// ---------------------------------------------------------------------------
// Static resources (created at load time — NOT during capture)
// ---------------------------------------------------------------------------
static cudaStream_t g_s2;
static cudaEvent_t  g_evFork, g_evJoin, g_evG1A, g_evGemm2A;
namespace {
struct StreamInit {
    StreamInit() {
        cudaStreamCreateWithFlags(&g_s2, cudaStreamNonBlocking);
        cudaEventCreateWithFlags(&g_evFork, cudaEventDisableTiming);
        cudaEventCreateWithFlags(&g_evJoin, cudaEventDisableTiming);
        cudaEventCreateWithFlags(&g_evG1A, cudaEventDisableTiming);
        cudaEventCreateWithFlags(&g_evGemm2A, cudaEventDisableTiming);
        cudaFuncSetAttribute(wmma_gemm_kernel<128, -1, BUF_XW1>,
                             cudaFuncAttributeMaxDynamicSharedMemorySize, WMMA_SMEM_128);
        cudaFuncSetAttribute(wmma_gemm_kernel<64, BUF_H1, BUF_XW2>,
                             cudaFuncAttributeMaxDynamicSharedMemorySize, WMMA_SMEM_64);
    }
};
static StreamInit g_streamInit;
}

// ---------------------------------------------------------------------------
extern "C" void kernel_launch(void* const* d_in, const int* in_sizes, int n_in,
                              void* d_out, int out_size) {
    const float* x     = (const float*)d_in[0];
    const int*   ei    = (const int*)d_in[1];
    const float* ew    = (const float*)d_in[2];
    const int*   batch = (const int*)d_in[3];
    const float* W1    = (const float*)d_in[4];
    const float* b1    = (const float*)d_in[5];
    const float* W2    = (const float*)d_in[6];
    const float* b2    = (const float*)d_in[7];
    const float* Wfc   = (const float*)d_in[8];
    const float* bfc   = (const float*)d_in[9];
    float* out = (float*)d_out;

    int N    = in_sizes[0] / 128;   // 40000
    int E    = in_sizes[2];         // 640000
    int flat = in_sizes[8] / 64;    // 2904
    int npart = (N + SCAN_CHUNK - 1) / SCAN_CHUNK;
    int tb = 256;
    int ngrid = (N + 127) / 128;    // 313

    // halves for gather1/gemm2 pipeline (A multiple of 128)
    int gridA = (ngrid + 1) / 2;    // 157
    int MA    = gridA * 128;        // 20096
    int gridB = ngrid - gridA;      // 156
    int MB    = N - MA;             // 19904

    // ---- fork: GEMM1 on s2, CSR prologue on default ----
    cudaEventRecord(g_evFork, 0);
    cudaStreamWaitEvent(g_s2, g_evFork, 0);

    wmma_gemm_kernel<128, -1, BUF_XW1><<<ngrid, 256, WMMA_SMEM_128, g_s2>>>(x, W1, N, 0);

    zero_kernel<<<(N + tb - 1) / tb, tb>>>(N);
    degree_kernel<<<(E + tb - 1) / tb, tb>>>(ei, ew, E);
    scan_part_kernel<<<npart, 256>>>(N);
    scan_final_kernel<<<npart, 256>>>(npart, N, E);
    build_kernel<<<(E + tb - 1) / tb, tb>>>(ei, ew, E);

    cudaEventRecord(g_evJoin, g_s2);
    cudaStreamWaitEvent(0, g_evJoin, 0);

    // ---- layer 1 aggregate / layer 2 GEMM pipeline ----
    // s0: g1(A) -> g1(B) -> gemm2(B);  s2: after g1(A): gemm2(A)
    gather_kernel<128, BUF_XW1, BUF_H1><<<(MA + 7) / 8, 256>>>(b1, 0, MA, N);
    cudaEventRecord(g_evG1A, 0);
    cudaStreamWaitEvent(g_s2, g_evG1A, 0);
    wmma_gemm_kernel<64, BUF_H1, BUF_XW2><<<gridA, 256, WMMA_SMEM_64, g_s2>>>(nullptr, W2, N, 0);
    cudaEventRecord(g_evGemm2A, g_s2);

    gather_kernel<128, BUF_XW1, BUF_H1><<<(MB + 7) / 8, 256>>>(b1, MA, MB, N);
    wmma_gemm_kernel<64, BUF_H1, BUF_XW2><<<gridB, 256, WMMA_SMEM_64>>>(nullptr, W2, N, MA);
    cudaStreamWaitEvent(0, g_evGemm2A, 0);

    // ---- layer 2 aggregate, pool (fused bounds), fc ----
    gather_kernel<64, BUF_XW2, BUF_H2><<<(N + 7) / 8, 256>>>(b2, 0, N, N);
    pool_kernel<<<NGRAPH, 256>>>(batch, N);
    fc_kernel<<<(NGRAPH * flat + tb - 1) / tb, tb>>>(Wfc, bfc, out, flat);
}